// round 7
// baseline (speedup 1.0000x reference)
#include <cuda_runtime.h>
#include <math.h>

#define B_SZ   2048
#define T_SZ   512
#define D_IN   64
#define H_SZ   128
#define D_OUT  64
#define M_TILE 16
#define NTHREADS 128
#define NSTEPS (T_SZ - 1)

// SMEM layout (floats):
//  [0      .. 16384)  Whh_t  (k-major: Whh_t[k*H+j] = W_hh[j*H+k])
//  [16384  .. 32768)  W1t    (reused post-loop for W_out_t)
//  [32768  .. 49152)  Pt     (k-major P^T view: Pt[k*H+j] = P[j][k], P = W1@W2)
//  [49152  .. 51200)  buf0   [16][128]
//  [51200  .. 53248)  buf1   [16][128]
//  [53248  .. 53376)  v_s
//  [53376  .. 53504)  c_s
//  [53504  .. 53632)  b1_s
//  [53632  .. 53760)  b2_s
//  [53760  .. 53888)  c1_s   (b2 @ W1^T)
//  [53888  .. 53904)  xs
#define OFF_WHH 0
#define OFF_W1  16384
#define OFF_P   32768
#define OFF_B0  49152
#define OFF_B1  51200
#define OFF_V   53248
#define OFF_C   53376
#define OFF_BB1 53504
#define OFF_BB2 53632
#define OFF_C1  53760
#define OFF_XS  53888
#define SMEM_FLOATS 53904
#define SMEM_BYTES  (SMEM_FLOATS * 4)   // 215616 B

// Precomputed by prep_kernel:
__device__ float g_P[H_SZ * H_SZ];    // g_P[k*H+j]   = sum_m W1[j][m] * W2[m][k]
__device__ float g_W2t[H_SZ * H_SZ];  // g_W2t[k*H+j] = W2[j][k]

__global__ void prep_kernel(const float* __restrict__ W1,
                            const float* __restrict__ W2) {
    __shared__ float w1row[H_SZ];
    const int j = blockIdx.x;
    const int k = threadIdx.x;
    w1row[k] = W1[j * H_SZ + k];
    __syncthreads();
    float s = 0.0f;
#pragma unroll 8
    for (int m = 0; m < H_SZ; m++)
        s = fmaf(w1row[m], W2[m * H_SZ + k], s);
    g_P[k * H_SZ + j]   = s;
    g_W2t[k * H_SZ + j] = W2[j * H_SZ + k];
}

__device__ __forceinline__ void gemm_acc(const float* __restrict__ Wt,
                                         const float* __restrict__ bufp,
                                         int rbase, int j0, float acc[4][4]) {
#pragma unroll 8
    for (int k = 0; k < H_SZ; k += 4) {
        const float4 w0 = *reinterpret_cast<const float4*>(Wt + (k + 0) * H_SZ + j0);
        const float4 w1 = *reinterpret_cast<const float4*>(Wt + (k + 1) * H_SZ + j0);
        const float4 w2 = *reinterpret_cast<const float4*>(Wt + (k + 2) * H_SZ + j0);
        const float4 w3 = *reinterpret_cast<const float4*>(Wt + (k + 3) * H_SZ + j0);
#pragma unroll
        for (int ri = 0; ri < 4; ri++) {
            const float4 a = *reinterpret_cast<const float4*>(bufp + (rbase + ri) * H_SZ + k);
            acc[ri][0] = fmaf(a.x, w0.x, acc[ri][0]);
            acc[ri][1] = fmaf(a.x, w0.y, acc[ri][1]);
            acc[ri][2] = fmaf(a.x, w0.z, acc[ri][2]);
            acc[ri][3] = fmaf(a.x, w0.w, acc[ri][3]);
            acc[ri][0] = fmaf(a.y, w1.x, acc[ri][0]);
            acc[ri][1] = fmaf(a.y, w1.y, acc[ri][1]);
            acc[ri][2] = fmaf(a.y, w1.z, acc[ri][2]);
            acc[ri][3] = fmaf(a.y, w1.w, acc[ri][3]);
            acc[ri][0] = fmaf(a.z, w2.x, acc[ri][0]);
            acc[ri][1] = fmaf(a.z, w2.y, acc[ri][1]);
            acc[ri][2] = fmaf(a.z, w2.z, acc[ri][2]);
            acc[ri][3] = fmaf(a.z, w2.w, acc[ri][3]);
            acc[ri][0] = fmaf(a.w, w3.x, acc[ri][0]);
            acc[ri][1] = fmaf(a.w, w3.y, acc[ri][1]);
            acc[ri][2] = fmaf(a.w, w3.z, acc[ri][2]);
            acc[ri][3] = fmaf(a.w, w3.w, acc[ri][3]);
        }
    }
}

// Same, but weights streamed from global (L2-resident).
__device__ __forceinline__ void gemm_acc_glb(const float* __restrict__ Wt,
                                             const float* __restrict__ bufp,
                                             int rbase, int j0, float acc[4][4]) {
#pragma unroll 8
    for (int k = 0; k < H_SZ; k += 4) {
        const float4 w0 = __ldg(reinterpret_cast<const float4*>(Wt + (k + 0) * H_SZ + j0));
        const float4 w1 = __ldg(reinterpret_cast<const float4*>(Wt + (k + 1) * H_SZ + j0));
        const float4 w2 = __ldg(reinterpret_cast<const float4*>(Wt + (k + 2) * H_SZ + j0));
        const float4 w3 = __ldg(reinterpret_cast<const float4*>(Wt + (k + 3) * H_SZ + j0));
#pragma unroll
        for (int ri = 0; ri < 4; ri++) {
            const float4 a = *reinterpret_cast<const float4*>(bufp + (rbase + ri) * H_SZ + k);
            acc[ri][0] = fmaf(a.x, w0.x, acc[ri][0]);
            acc[ri][1] = fmaf(a.x, w0.y, acc[ri][1]);
            acc[ri][2] = fmaf(a.x, w0.z, acc[ri][2]);
            acc[ri][3] = fmaf(a.x, w0.w, acc[ri][3]);
            acc[ri][0] = fmaf(a.y, w1.x, acc[ri][0]);
            acc[ri][1] = fmaf(a.y, w1.y, acc[ri][1]);
            acc[ri][2] = fmaf(a.y, w1.z, acc[ri][2]);
            acc[ri][3] = fmaf(a.y, w1.w, acc[ri][3]);
            acc[ri][0] = fmaf(a.z, w2.x, acc[ri][0]);
            acc[ri][1] = fmaf(a.z, w2.y, acc[ri][1]);
            acc[ri][2] = fmaf(a.z, w2.z, acc[ri][2]);
            acc[ri][3] = fmaf(a.z, w2.w, acc[ri][3]);
            acc[ri][0] = fmaf(a.w, w3.x, acc[ri][0]);
            acc[ri][1] = fmaf(a.w, w3.y, acc[ri][1]);
            acc[ri][2] = fmaf(a.w, w3.z, acc[ri][2]);
            acc[ri][3] = fmaf(a.w, w3.w, acc[ri][3]);
        }
    }
}

__device__ __forceinline__ void stage4(float* __restrict__ bufp, int rbase, int j0,
                                       const float v[4][4]) {
#pragma unroll
    for (int ri = 0; ri < 4; ri++) {
        *reinterpret_cast<float4*>(bufp + (rbase + ri) * H_SZ + j0) =
            make_float4(v[ri][0], v[ri][1], v[ri][2], v[ri][3]);
    }
}

__device__ __forceinline__ float silu_f(float v) {
    return v / (1.0f + __expf(-v));
}

__global__ void __launch_bounds__(NTHREADS, 1)
rnnode_kernel(const float* __restrict__ x, const float* __restrict__ span,
              const float* __restrict__ W_emb, const float* __restrict__ b_emb,
              const float* __restrict__ W_ih, const float* __restrict__ b_ih,
              const float* __restrict__ W_hh, const float* __restrict__ b_hh,
              const float* __restrict__ W1, const float* __restrict__ b1,
              const float* __restrict__ W2, const float* __restrict__ b2,
              const float* __restrict__ W_out, const float* __restrict__ b_out,
              float* __restrict__ out) {
    extern __shared__ float sm[];
    float* Whh_t = sm + OFF_WHH;
    float* W1t   = sm + OFF_W1;
    float* Pt    = sm + OFF_P;
    float* buf0  = sm + OFF_B0;
    float* buf1  = sm + OFF_B1;
    float* v_s   = sm + OFF_V;
    float* c_s   = sm + OFF_C;
    float* b1_s  = sm + OFF_BB1;
    float* b2_s  = sm + OFF_BB2;
    float* c1_s  = sm + OFF_C1;
    float* xs    = sm + OFF_XS;

    const int tid = threadIdx.x;
    const int b0  = blockIdx.x * M_TILE;

    // Load weights transposed to k-major; P already k-major in global.
    for (int i = tid; i < H_SZ * H_SZ; i += NTHREADS) {
        const int j = i >> 7, k = i & 127;
        Whh_t[k * H_SZ + j] = W_hh[i];
        W1t[k * H_SZ + j]   = W1[i];
        Pt[i] = g_P[i];
    }
    // Fold input path + aux vectors.
    if (tid < H_SZ) {
        float vv = 0.0f, cc = 0.0f;
        for (int d = 0; d < D_IN; d++) {
            const float w = W_ih[tid * D_IN + d];
            vv = fmaf(w, W_emb[d], vv);
            cc = fmaf(w, b_emb[d], cc);
        }
        v_s[tid]  = vv;
        c_s[tid]  = cc + b_ih[tid] + b_hh[tid];
        b1_s[tid] = b1[tid];
        b2_s[tid] = b2[tid];
        // c1 = b2 @ W1^T : c1[j] = sum_k b2[k] * W1[j][k]
        float c1v = 0.0f;
        for (int k = 0; k < H_SZ; k++)
            c1v = fmaf(b2[k], W1[tid * H_SZ + k], c1v);
        c1_s[tid] = c1v;
    }
    __syncthreads();

    const int rg    = tid >> 5;
    const int lane  = tid & 31;
    const int rbase = rg * 4;
    const int j0    = lane * 4;

    const float4 b1v = *reinterpret_cast<const float4*>(b1_s + j0);
    const float4 b2v = *reinterpret_cast<const float4*>(b2_s + j0);
    const float4 c1v = *reinterpret_cast<const float4*>(c1_s + j0);
    const float4 vv  = *reinterpret_cast<const float4*>(v_s + j0);
    const float4 cc  = *reinterpret_cast<const float4*>(c_s + j0);
    const float b1a[4] = {b1v.x, b1v.y, b1v.z, b1v.w};
    const float b2a[4] = {b2v.x, b2v.y, b2v.z, b2v.w};
    const float c1a[4] = {c1v.x, c1v.y, c1v.z, c1v.w};

    float h[4][4];
#pragma unroll
    for (int ri = 0; ri < 4; ri++)
#pragma unroll
        for (int c = 0; c < 4; c++) h[ri][c] = 0.0f;

    int p = 0;
#define BUF(pp) ((pp) ? buf1 : buf0)

    for (int t = 0; t < NSTEPS; t++) {
        const float dt   = __ldg(span + t + 1) - __ldg(span + t);
        const float dt3  = dt * (1.0f / 3.0f);
        const float dt23 = dt3 * 2.0f;
        const float dt8  = dt * 0.125f;

        float acc[4][4];
        float z1[4][4], u1[4][4], u2[4][4], u3[4][4];

        // ---- G1: h = tanh(x*v + c + h @ Whh^T) ----
        stage4(BUF(p), rbase, j0, h);
        if (tid < M_TILE) xs[tid] = x[(size_t)(b0 + tid) * T_SZ + t];
        __syncthreads();
#pragma unroll
        for (int ri = 0; ri < 4; ri++) {
            const float xv = xs[rbase + ri];
            acc[ri][0] = fmaf(xv, vv.x, cc.x);
            acc[ri][1] = fmaf(xv, vv.y, cc.y);
            acc[ri][2] = fmaf(xv, vv.z, cc.z);
            acc[ri][3] = fmaf(xv, vv.w, cc.w);
        }
        gemm_acc(Whh_t, BUF(p), rbase, j0, acc);
        p ^= 1;
#pragma unroll
        for (int ri = 0; ri < 4; ri++)
#pragma unroll
            for (int c = 0; c < 4; c++) h[ri][c] = tanhf(acc[ri][c]);

        // ---- G2: z1 = h @ W1^T + b1 ; u1 = silu(z1) ----
        stage4(BUF(p), rbase, j0, h);
        __syncthreads();
#pragma unroll
        for (int ri = 0; ri < 4; ri++)
#pragma unroll
            for (int c = 0; c < 4; c++) acc[ri][c] = b1a[c];
        gemm_acc(W1t, BUF(p), rbase, j0, acc);
        p ^= 1;
#pragma unroll
        for (int ri = 0; ri < 4; ri++)
#pragma unroll
            for (int c = 0; c < 4; c++) {
                z1[ri][c] = acc[ri][c];
                u1[ri][c] = silu_f(acc[ri][c]);
            }

        // ---- G3: z2 = z1 + dt/3*(u1 @ P^T + c1) ; u2 = silu(z2) ----
        stage4(BUF(p), rbase, j0, u1);
        __syncthreads();
#pragma unroll
        for (int ri = 0; ri < 4; ri++)
#pragma unroll
            for (int c = 0; c < 4; c++) acc[ri][c] = c1a[c];
        gemm_acc(Pt, BUF(p), rbase, j0, acc);
        p ^= 1;
#pragma unroll
        for (int ri = 0; ri < 4; ri++)
#pragma unroll
            for (int c = 0; c < 4; c++)
                u2[ri][c] = silu_f(fmaf(dt3, acc[ri][c], z1[ri][c]));

        // ---- G4: z3 = z1 + dt*((u2 - u1/3) @ P^T) + (2dt/3)*c1 ; u3 ----
        {
            float g2[4][4];
#pragma unroll
            for (int ri = 0; ri < 4; ri++)
#pragma unroll
                for (int c = 0; c < 4; c++)
                    g2[ri][c] = fmaf(-(1.0f / 3.0f), u1[ri][c], u2[ri][c]);
            stage4(BUF(p), rbase, j0, g2);
        }
        __syncthreads();
#pragma unroll
        for (int ri = 0; ri < 4; ri++)
#pragma unroll
            for (int c = 0; c < 4; c++) acc[ri][c] = 0.0f;
        gemm_acc(Pt, BUF(p), rbase, j0, acc);
        p ^= 1;
#pragma unroll
        for (int ri = 0; ri < 4; ri++)
#pragma unroll
            for (int c = 0; c < 4; c++)
                u3[ri][c] = silu_f(fmaf(dt, acc[ri][c],
                                        fmaf(dt23, c1a[c], z1[ri][c])));

        // ---- G5: z4 = z1 + dt*((u1 - u2 + u3) @ P^T + c1) ; u4 -> g4 ----
        {
            float g3[4][4];
#pragma unroll
            for (int ri = 0; ri < 4; ri++)
#pragma unroll
                for (int c = 0; c < 4; c++)
                    g3[ri][c] = u1[ri][c] - u2[ri][c] + u3[ri][c];
            stage4(BUF(p), rbase, j0, g3);
        }
        __syncthreads();
#pragma unroll
        for (int ri = 0; ri < 4; ri++)
#pragma unroll
            for (int c = 0; c < 4; c++) acc[ri][c] = c1a[c];
        gemm_acc(Pt, BUF(p), rbase, j0, acc);
        p ^= 1;

        // ---- G6: h += (dt/8)*(g4 @ W2^T) + dt*b2, g4 = u1+3(u2+u3)+u4 ----
        {
            float g4[4][4];
#pragma unroll
            for (int ri = 0; ri < 4; ri++)
#pragma unroll
                for (int c = 0; c < 4; c++) {
                    const float z4 = fmaf(dt, acc[ri][c], z1[ri][c]);
                    const float u4 = silu_f(z4);
                    g4[ri][c] = fmaf(3.0f, u2[ri][c] + u3[ri][c],
                                     u1[ri][c] + u4);
                }
            stage4(BUF(p), rbase, j0, g4);
        }
        __syncthreads();
#pragma unroll
        for (int ri = 0; ri < 4; ri++)
#pragma unroll
            for (int c = 0; c < 4; c++) acc[ri][c] = 0.0f;
        gemm_acc_glb(g_W2t, BUF(p), rbase, j0, acc);
        p ^= 1;
#pragma unroll
        for (int ri = 0; ri < 4; ri++)
#pragma unroll
            for (int c = 0; c < 4; c++)
                h[ri][c] = fmaf(dt8, acc[ri][c],
                                fmaf(dt, b2a[c], h[ri][c]));
    }

    // ---- out = h @ W_out^T + b_out ----
    __syncthreads();
    for (int i = tid; i < D_OUT * H_SZ; i += NTHREADS) {
        const int j = i >> 7, k = i & 127;
        W1t[k * D_OUT + j] = W_out[i];
    }
    float* bp = BUF(p);
    stage4(bp, rbase, j0, h);
    __syncthreads();

    const int jo = lane * 2;
#pragma unroll
    for (int ri = 0; ri < 4; ri++) {
        float o0 = __ldg(b_out + jo);
        float o1 = __ldg(b_out + jo + 1);
        const float* br = bp + (rbase + ri) * H_SZ;
#pragma unroll 16
        for (int k = 0; k < H_SZ; k++) {
            const float a = br[k];
            const float2 w = *reinterpret_cast<const float2*>(W1t + k * D_OUT + jo);
            o0 = fmaf(a, w.x, o0);
            o1 = fmaf(a, w.y, o1);
        }
        *reinterpret_cast<float2*>(out + (size_t)(b0 + rbase + ri) * D_OUT + jo) =
            make_float2(o0, o1);
    }
}

extern "C" void kernel_launch(void* const* d_in, const int* in_sizes, int n_in,
                              void* d_out, int out_size) {
    const float* x     = (const float*)d_in[0];
    const float* span  = (const float*)d_in[1];
    const float* W_emb = (const float*)d_in[2];
    const float* b_emb = (const float*)d_in[3];
    const float* W_ih  = (const float*)d_in[4];
    const float* b_ih  = (const float*)d_in[5];
    const float* W_hh  = (const float*)d_in[6];
    const float* b_hh  = (const float*)d_in[7];
    const float* W1    = (const float*)d_in[8];
    const float* b1    = (const float*)d_in[9];
    const float* W2    = (const float*)d_in[10];
    const float* b2    = (const float*)d_in[11];
    const float* W_out = (const float*)d_in[12];
    const float* b_out = (const float*)d_in[13];
    float* out = (float*)d_out;

    prep_kernel<<<H_SZ, H_SZ>>>(W1, W2);
    cudaFuncSetAttribute(rnnode_kernel,
                         cudaFuncAttributeMaxDynamicSharedMemorySize, SMEM_BYTES);
    rnnode_kernel<<<B_SZ / M_TILE, NTHREADS, SMEM_BYTES>>>(
        x, span, W_emb, b_emb, W_ih, b_ih, W_hh, b_hh,
        W1, b1, W2, b2, W_out, b_out, out);
}

// round 10
// speedup vs baseline: 2.5447x; 2.5447x over previous
#include <cuda_runtime.h>
#include <cuda_bf16.h>
#include <stdint.h>
#include <math.h>

#define B_SZ 2048
#define T_SZ 512
#define D_IN 64
#define H    128
#define D_OUT 64
#define NB   16
#define NTH  256
#define NSTEPS (T_SZ-1)
#define ROWB 528   // activation buffer row stride in bytes (264 bf16)

// SMEM byte offsets
#define SM_WF0 0        // Whh fragments (64KB)
#define SM_WF1 65536    // W1 fragments
#define SM_WF2 131072   // W2 fragments
#define SM_AB0 196608   // activation ping  [16][264] bf16
#define SM_AB1 205056   // activation pong
#define SM_XS  213504   // 16 floats
#define SMEM_BYTES 213568

__device__ __forceinline__ uint32_t smem_u32(const void* p) {
    uint32_t a;
    asm("{ .reg .u64 t; cvta.to.shared.u64 t, %1; cvt.u32.u64 %0, t; }" : "=r"(a) : "l"(p));
    return a;
}
__device__ __forceinline__ uint32_t pkbf(float a, float b) {
    __nv_bfloat16 ha = __float2bfloat16(a), hb = __float2bfloat16(b);
    return (uint32_t)__bfloat16_as_ushort(ha) | ((uint32_t)__bfloat16_as_ushort(hb) << 16);
}
__device__ __forceinline__ void ldsm4(uint32_t& r0, uint32_t& r1, uint32_t& r2,
                                      uint32_t& r3, uint32_t addr) {
    asm volatile("ldmatrix.sync.aligned.m8n8.x4.shared.b16 {%0,%1,%2,%3}, [%4];"
                 : "=r"(r0), "=r"(r1), "=r"(r2), "=r"(r3) : "r"(addr));
}
__device__ __forceinline__ void mma_bf16(float* d, uint32_t a0, uint32_t a1,
                                         uint32_t a2, uint32_t a3,
                                         uint32_t b0, uint32_t b1) {
    asm volatile("mma.sync.aligned.m16n8k16.row.col.f32.bf16.bf16.f32 "
                 "{%0,%1,%2,%3}, {%4,%5,%6,%7}, {%8,%9}, {%0,%1,%2,%3};"
                 : "+f"(d[0]), "+f"(d[1]), "+f"(d[2]), "+f"(d[3])
                 : "r"(a0), "r"(a1), "r"(a2), "r"(a3), "r"(b0), "r"(b1));
}
__device__ __forceinline__ float silu_f(float v) {
    return __fdividef(v, 1.0f + __expf(-v));
}

// Stage 8 fragment values (2 tiles x {d0(r0,c),d1(r0,c+1),d2(r1,c),d3(r1,c+1)})
// into activation buffer as bf16 hi (col k) and lo (col k+128 -> +256 bytes).
__device__ __forceinline__ void stage8(char* ab, const float* v,
                                       uint32_t o00, uint32_t o10) {
#pragma unroll
    for (int ntl = 0; ntl < 2; ntl++) {
        const float d0 = v[ntl*4+0], d1 = v[ntl*4+1];
        const float d2 = v[ntl*4+2], d3 = v[ntl*4+3];
        const uint32_t oa = o00 + ntl*16, ob = o10 + ntl*16;
        const __nv_bfloat16 h0 = __float2bfloat16(d0), h1 = __float2bfloat16(d1);
        const __nv_bfloat16 h2 = __float2bfloat16(d2), h3 = __float2bfloat16(d3);
        *(uint32_t*)(ab + oa) = (uint32_t)__bfloat16_as_ushort(h0) |
                                ((uint32_t)__bfloat16_as_ushort(h1) << 16);
        *(uint32_t*)(ab + ob) = (uint32_t)__bfloat16_as_ushort(h2) |
                                ((uint32_t)__bfloat16_as_ushort(h3) << 16);
        *(uint32_t*)(ab + oa + 256) = pkbf(d0 - __bfloat162float(h0),
                                           d1 - __bfloat162float(h1));
        *(uint32_t*)(ab + ob + 256) = pkbf(d2 - __bfloat162float(h2),
                                           d3 - __bfloat162float(h3));
    }
}

// One [16,128]x[128,128]^T GEMM: 8 ksteps x 2 ntiles x 3 split-terms of HMMA.
__device__ __forceinline__ void gemm48(uint32_t ab_u32, uint32_t aoff,
                                       const char* wf, uint32_t boff,
                                       float* acc) {
#pragma unroll
    for (int s = 0; s < 8; s++) {
        uint32_t ah0, ah1, ah2, ah3, al0, al1, al2, al3;
        const uint32_t aa = ab_u32 + aoff + s*32;
        ldsm4(ah0, ah1, ah2, ah3, aa);
        ldsm4(al0, al1, al2, al3, aa + 256);
#pragma unroll
        for (int ntl = 0; ntl < 2; ntl++) {
            const char* bb = wf + boff + ntl*4096 + s*256;
            const uint2 bh = *(const uint2*)bb;
            const uint2 bl = *(const uint2*)(bb + 2048);
            float* d = acc + ntl*4;
            mma_bf16(d, ah0, ah1, ah2, ah3, bh.x, bh.y);
            mma_bf16(d, ah0, ah1, ah2, ah3, bl.x, bl.y);
            mma_bf16(d, al0, al1, al2, al3, bh.x, bh.y);
        }
    }
}

__global__ void __launch_bounds__(NTH, 1)
rnnode_mma(const float* __restrict__ x, const float* __restrict__ span,
           const float* __restrict__ W_emb, const float* __restrict__ b_emb,
           const float* __restrict__ W_ih, const float* __restrict__ b_ih,
           const float* __restrict__ W_hh, const float* __restrict__ b_hh,
           const float* __restrict__ W1, const float* __restrict__ b1,
           const float* __restrict__ W2, const float* __restrict__ b2,
           const float* __restrict__ W_out, const float* __restrict__ b_out,
           float* __restrict__ out) {
    extern __shared__ char smc[];
    const uint32_t smb = smem_u32(smc);
    const int tid = threadIdx.x;
    const int lane = tid & 31, wid = tid >> 5;
    const int bb0 = blockIdx.x * NB;
    float* xs = (float*)(smc + SM_XS);

    // ---- fill weight fragment buffers (B-fragment order) ----
#pragma unroll 1
    for (int m = 0; m < 3; m++) {
        const float* W = (m == 0) ? W_hh : (m == 1) ? W1 : W2;
        char* wf = smc + (m == 0 ? SM_WF0 : m == 1 ? SM_WF1 : SM_WF2);
        for (int fi = tid; fi < 4096; fi += NTH) {
            const int ntile = fi >> 8, ks = (fi >> 5) & 7, ln = fi & 31;
            const int n = ntile * 8 + (ln >> 2);
            const int k0 = ks * 16 + 2 * (ln & 3);
            const float w00 = W[n*H + k0],     w01 = W[n*H + k0 + 1];
            const float w10 = W[n*H + k0 + 8], w11 = W[n*H + k0 + 9];
            const __nv_bfloat16 a00 = __float2bfloat16(w00), a01 = __float2bfloat16(w01);
            const __nv_bfloat16 a10 = __float2bfloat16(w10), a11 = __float2bfloat16(w11);
            uint2 hi, lo;
            hi.x = (uint32_t)__bfloat16_as_ushort(a00) | ((uint32_t)__bfloat16_as_ushort(a01) << 16);
            hi.y = (uint32_t)__bfloat16_as_ushort(a10) | ((uint32_t)__bfloat16_as_ushort(a11) << 16);
            lo.x = pkbf(w00 - __bfloat162float(a00), w01 - __bfloat162float(a01));
            lo.y = pkbf(w10 - __bfloat162float(a10), w11 - __bfloat162float(a11));
            const uint32_t base = ntile*4096 + ks*256 + ln*8;
            *(uint2*)(wf + base)        = hi;
            *(uint2*)(wf + base + 2048) = lo;
        }
    }

    // ---- per-thread fragment geometry ----
    const int g = lane >> 2, tq = lane & 3;
    const int r0 = g, r1 = g + 8;
    const int cb0 = wid * 16 + 2 * tq;             // tile0 col c
    const uint32_t o00 = (uint32_t)(r0 * ROWB + cb0 * 2);
    const uint32_t o10 = (uint32_t)(r1 * ROWB + cb0 * 2);
    const uint32_t arow = (uint32_t)((((lane >> 3) & 1) * 8) + (lane & 7));
    const uint32_t aoff = arow * ROWB + (((lane >> 4) & 1) * 8) * 2;
    const uint32_t boff = (uint32_t)((wid * 2) * 4096 + lane * 8);

    // ---- per-element constants for the 4 distinct cols {cb0,cb0+1,cb0+8,cb0+9} ----
    float cv[4], ccst[4], cb1[4], cb2[4];
#pragma unroll
    for (int q = 0; q < 4; q++) {
        const int col = cb0 + (q >> 1) * 8 + (q & 1);
        float vv = 0.0f, cc = 0.0f;
        for (int d = 0; d < D_IN; d++) {
            const float w = W_ih[col * D_IN + d];
            vv = fmaf(w, W_emb[d], vv);
            cc = fmaf(w, b_emb[d], cc);
        }
        cv[q] = vv;
        ccst[q] = cc + b_ih[col] + b_hh[col];
        cb1[q] = b1[col];
        cb2[q] = b2[col];
    }
    // frag index i = ntl*4 + j ; col sel q = ntl*2 + (j&1) ; row sel = j>>1
    __syncthreads();

    const uint32_t abu[2] = {smb + SM_AB0, smb + SM_AB1};
    char* abp[2] = {smc + SM_AB0, smc + SM_AB1};
    const char* wf0 = smc + SM_WF0;
    const char* wf1 = smc + SM_WF1;
    const char* wf2 = smc + SM_WF2;

    float h[8], k1[8], kt[8], ksm[8], y[8];
#pragma unroll
    for (int i = 0; i < 8; i++) h[i] = 0.0f;
    int p = 0;

#define QSEL(i) (((i) >> 2) * 2 + ((i) & 1))
#define RSEL(i) ((((i) >> 1) & 1))

#define FEVAL(OUT, IN) do {                                                   \
        stage8(abp[p], IN, o00, o10);                                         \
        __syncthreads();                                                      \
        float a1_[8] = {0,0,0,0,0,0,0,0};                                     \
        gemm48(abu[p], aoff, wf1, boff, a1_);                                 \
        p ^= 1;                                                               \
        float u_[8];                                                          \
        _Pragma("unroll")                                                     \
        for (int i = 0; i < 8; i++) u_[i] = silu_f(a1_[i] + cb1[QSEL(i)]);    \
        stage8(abp[p], u_, o00, o10);                                         \
        __syncthreads();                                                      \
        float a2_[8] = {0,0,0,0,0,0,0,0};                                     \
        gemm48(abu[p], aoff, wf2, boff, a2_);                                 \
        p ^= 1;                                                               \
        _Pragma("unroll")                                                     \
        for (int i = 0; i < 8; i++) OUT[i] = a2_[i] + cb2[QSEL(i)];           \
    } while (0)

#pragma unroll 1
    for (int t = 0; t < NSTEPS; t++) {
        const float dt  = __ldg(span + t + 1) - __ldg(span + t);
        const float dt3 = dt * (1.0f / 3.0f);
        const float dt8 = dt * 0.125f;

        if (tid < NB) xs[tid] = x[(size_t)(bb0 + tid) * T_SZ + t];

        // G1: h = tanh(x*v + c + h@Whh^T)
        stage8(abp[p], h, o00, o10);
        __syncthreads();
        {
            float a0_[8] = {0,0,0,0,0,0,0,0};
            gemm48(abu[p], aoff, wf0, boff, a0_);
            p ^= 1;
            const float xr[2] = {xs[r0], xs[r1]};
#pragma unroll
            for (int i = 0; i < 8; i++) {
                const int q = QSEL(i);
                h[i] = tanhf(a0_[i] + fmaf(xr[RSEL(i)], cv[q], ccst[q]));
            }
        }
        // RK4 (3/8 rule)
        FEVAL(k1, h);
#pragma unroll
        for (int i = 0; i < 8; i++) y[i] = fmaf(dt3, k1[i], h[i]);
        FEVAL(kt, y);   // k2
#pragma unroll
        for (int i = 0; i < 8; i++) {
            ksm[i] = 3.0f * kt[i];
            y[i] = fmaf(dt, kt[i], fmaf(-dt3, k1[i], h[i]));
            kt[i] = k1[i] - kt[i];                 // k1 - k2
        }
        FEVAL(y, y);    // y = k3
#pragma unroll
        for (int i = 0; i < 8; i++) {
            ksm[i] = k1[i] + 3.0f * y[i] + ksm[i]; // k1 + 3(k2+k3)
            kt[i] = fmaf(dt, kt[i] + y[i], h[i]);  // h + dt(k1-k2+k3)
        }
        FEVAL(y, kt);   // y = k4
#pragma unroll
        for (int i = 0; i < 8; i++) h[i] = fmaf(dt8, ksm[i] + y[i], h[i]);
    }

    // ---- epilogue: out = h @ W_out^T + b_out ----
    __syncthreads();
    float* hb = (float*)smc;  // reuse WF0 region: [16][128] fp32
#pragma unroll
    for (int ntl = 0; ntl < 2; ntl++) {
        const int c = cb0 + ntl * 8;
        hb[r0 * H + c]     = h[ntl*4+0];
        hb[r0 * H + c + 1] = h[ntl*4+1];
        hb[r1 * H + c]     = h[ntl*4+2];
        hb[r1 * H + c + 1] = h[ntl*4+3];
    }
    __syncthreads();
    {
        const int j = tid & 63, q = tid >> 6;
        float o[4];
        const float bo = __ldg(b_out + j);
#pragma unroll
        for (int n = 0; n < 4; n++) o[n] = bo;
        const float* Wo = W_out + j * H;
#pragma unroll 4
        for (int k = 0; k < H; k++) {
            const float wv = __ldg(Wo + k);
            const float* ar = hb + (q * 4) * H + k;
#pragma unroll
            for (int n = 0; n < 4; n++) o[n] = fmaf(ar[n * H], wv, o[n]);
        }
#pragma unroll
        for (int n = 0; n < 4; n++)
            out[(size_t)(bb0 + q * 4 + n) * D_OUT + j] = o[n];
    }
}

extern "C" void kernel_launch(void* const* d_in, const int* in_sizes, int n_in,
                              void* d_out, int out_size) {
    const float* x     = (const float*)d_in[0];
    const float* span  = (const float*)d_in[1];
    const float* W_emb = (const float*)d_in[2];
    const float* b_emb = (const float*)d_in[3];
    const float* W_ih  = (const float*)d_in[4];
    const float* b_ih  = (const float*)d_in[5];
    const float* W_hh  = (const float*)d_in[6];
    const float* b_hh  = (const float*)d_in[7];
    const float* W1    = (const float*)d_in[8];
    const float* b1    = (const float*)d_in[9];
    const float* W2    = (const float*)d_in[10];
    const float* b2    = (const float*)d_in[11];
    const float* W_out = (const float*)d_in[12];
    const float* b_out = (const float*)d_in[13];
    float* out = (float*)d_out;

    cudaFuncSetAttribute(rnnode_mma, cudaFuncAttributeMaxDynamicSharedMemorySize,
                         SMEM_BYTES);
    rnnode_mma<<<B_SZ / NB, NTH, SMEM_BYTES>>>(
        x, span, W_emb, b_emb, W_ih, b_ih, W_hh, b_hh,
        W1, b1, W2, b2, W_out, b_out, out);
}

// round 11
// speedup vs baseline: 3.4793x; 1.3673x over previous
#include <cuda_runtime.h>
#include <cuda_bf16.h>
#include <stdint.h>
#include <math.h>

#define B_SZ 2048
#define T_SZ 512
#define D_IN 64
#define H    128
#define D_OUT 64
#define NB   16
#define NTH  256
#define NSTEPS (T_SZ-1)
#define ROWB 528   // activation buffer row stride in bytes (264 bf16)

// SMEM byte offsets
#define SM_WF0 0        // Whh fragments (64KB)
#define SM_WF1 65536    // W1 fragments
#define SM_WFP 131072   // P fragments
#define SM_AB0 196608   // activation ping  [16][264] bf16
#define SM_AB1 205056   // activation pong
#define SM_XS  213504   // 16 floats
#define SMEM_BYTES 213568

__device__ float g_P[H * H];              // P[j][k] = sum_m W1[j][m] W2[m][k]
__device__ unsigned long long g_W2f[8192]; // W2 fragments (64KB, hi/lo blocks)

__device__ __forceinline__ uint32_t smem_u32(const void* p) {
    uint32_t a;
    asm("{ .reg .u64 t; cvta.to.shared.u64 t, %1; cvt.u32.u64 %0, t; }" : "=r"(a) : "l"(p));
    return a;
}
__device__ __forceinline__ uint32_t pkbf(float a, float b) {
    __nv_bfloat16 ha = __float2bfloat16(a), hb = __float2bfloat16(b);
    return (uint32_t)__bfloat16_as_ushort(ha) | ((uint32_t)__bfloat16_as_ushort(hb) << 16);
}
__device__ __forceinline__ void ldsm4(uint32_t& r0, uint32_t& r1, uint32_t& r2,
                                      uint32_t& r3, uint32_t addr) {
    asm volatile("ldmatrix.sync.aligned.m8n8.x4.shared.b16 {%0,%1,%2,%3}, [%4];"
                 : "=r"(r0), "=r"(r1), "=r"(r2), "=r"(r3) : "r"(addr));
}
__device__ __forceinline__ void mma_bf16(float* d, uint32_t a0, uint32_t a1,
                                         uint32_t a2, uint32_t a3,
                                         uint32_t b0, uint32_t b1) {
    asm volatile("mma.sync.aligned.m16n8k16.row.col.f32.bf16.bf16.f32 "
                 "{%0,%1,%2,%3}, {%4,%5,%6,%7}, {%8,%9}, {%0,%1,%2,%3};"
                 : "+f"(d[0]), "+f"(d[1]), "+f"(d[2]), "+f"(d[3])
                 : "r"(a0), "r"(a1), "r"(a2), "r"(a3), "r"(b0), "r"(b1));
}
__device__ __forceinline__ float silu_f(float v) {
    return __fdividef(v, 1.0f + __expf(-v));
}

// Stage 8 fragment values into activation buffer as bf16 hi (+0) / lo (+256B).
__device__ __forceinline__ void stage8(char* ab, const float* v,
                                       uint32_t o00, uint32_t o10) {
#pragma unroll
    for (int ntl = 0; ntl < 2; ntl++) {
        const float d0 = v[ntl*4+0], d1 = v[ntl*4+1];
        const float d2 = v[ntl*4+2], d3 = v[ntl*4+3];
        const uint32_t oa = o00 + ntl*16, ob = o10 + ntl*16;
        const __nv_bfloat16 h0 = __float2bfloat16(d0), h1 = __float2bfloat16(d1);
        const __nv_bfloat16 h2 = __float2bfloat16(d2), h3 = __float2bfloat16(d3);
        *(uint32_t*)(ab + oa) = (uint32_t)__bfloat16_as_ushort(h0) |
                                ((uint32_t)__bfloat16_as_ushort(h1) << 16);
        *(uint32_t*)(ab + ob) = (uint32_t)__bfloat16_as_ushort(h2) |
                                ((uint32_t)__bfloat16_as_ushort(h3) << 16);
        *(uint32_t*)(ab + oa + 256) = pkbf(d0 - __bfloat162float(h0),
                                           d1 - __bfloat162float(h1));
        *(uint32_t*)(ab + ob + 256) = pkbf(d2 - __bfloat162float(h2),
                                           d3 - __bfloat162float(h3));
    }
}

// GEMM, B from SMEM, 3 accumulator groups (term-split -> 8-deep HMMA chains).
__device__ __forceinline__ void gemm48s(uint32_t ab_u32, uint32_t aoff,
                                        const char* wf, uint32_t boff,
                                        float* dout) {
    float a0[8], a1[8], a2[8];
#pragma unroll
    for (int i = 0; i < 8; i++) { a0[i] = 0.f; a1[i] = 0.f; a2[i] = 0.f; }
#pragma unroll
    for (int s = 0; s < 8; s++) {
        uint32_t ah0, ah1, ah2, ah3, al0, al1, al2, al3;
        const uint32_t aa = ab_u32 + aoff + s*32;
        ldsm4(ah0, ah1, ah2, ah3, aa);
        ldsm4(al0, al1, al2, al3, aa + 256);
#pragma unroll
        for (int ntl = 0; ntl < 2; ntl++) {
            const char* bb = wf + boff + ntl*4096 + s*256;
            const uint2 bh = *(const uint2*)bb;
            const uint2 bl = *(const uint2*)(bb + 2048);
            mma_bf16(a0 + ntl*4, ah0, ah1, ah2, ah3, bh.x, bh.y);
            mma_bf16(a1 + ntl*4, ah0, ah1, ah2, ah3, bl.x, bl.y);
            mma_bf16(a2 + ntl*4, al0, al1, al2, al3, bh.x, bh.y);
        }
    }
#pragma unroll
    for (int i = 0; i < 8; i++) dout[i] = a0[i] + a1[i] + a2[i];
}

// GEMM, B streamed from global (L2). All 32 B-frag loads issued up front.
__device__ __forceinline__ void gemm48g(uint32_t ab_u32, uint32_t aoff,
                                        const char* gw, uint32_t boff,
                                        float* dout) {
    uint2 BH[16], BL[16];
#pragma unroll
    for (int s = 0; s < 8; s++) {
#pragma unroll
        for (int ntl = 0; ntl < 2; ntl++) {
            const char* bb = gw + boff + ntl*4096 + s*256;
            BH[s*2+ntl] = __ldg((const uint2*)bb);
            BL[s*2+ntl] = __ldg((const uint2*)(bb + 2048));
        }
    }
    float a0[8], a1[8], a2[8];
#pragma unroll
    for (int i = 0; i < 8; i++) { a0[i] = 0.f; a1[i] = 0.f; a2[i] = 0.f; }
#pragma unroll
    for (int s = 0; s < 8; s++) {
        uint32_t ah0, ah1, ah2, ah3, al0, al1, al2, al3;
        const uint32_t aa = ab_u32 + aoff + s*32;
        ldsm4(ah0, ah1, ah2, ah3, aa);
        ldsm4(al0, al1, al2, al3, aa + 256);
#pragma unroll
        for (int ntl = 0; ntl < 2; ntl++) {
            const uint2 bh = BH[s*2+ntl];
            const uint2 bl = BL[s*2+ntl];
            mma_bf16(a0 + ntl*4, ah0, ah1, ah2, ah3, bh.x, bh.y);
            mma_bf16(a1 + ntl*4, ah0, ah1, ah2, ah3, bl.x, bl.y);
            mma_bf16(a2 + ntl*4, al0, al1, al2, al3, bh.x, bh.y);
        }
    }
#pragma unroll
    for (int i = 0; i < 8; i++) dout[i] = a0[i] + a1[i] + a2[i];
}

// ---- prep kernels ----
__global__ void prep_p(const float* __restrict__ W1, const float* __restrict__ W2) {
    __shared__ float w1row[H];
    const int j = blockIdx.x, k = threadIdx.x;
    w1row[k] = W1[j * H + k];
    __syncthreads();
    float s = 0.0f;
#pragma unroll 8
    for (int m = 0; m < H; m++) s = fmaf(w1row[m], W2[m * H + k], s);
    g_P[j * H + k] = s;   // row-major P[j][k]
}

__global__ void prep_frag(const float* __restrict__ W2) {
    const int fi = blockIdx.x * blockDim.x + threadIdx.x;  // 0..4095
    const int ntile = fi >> 8, ks = (fi >> 5) & 7, ln = fi & 31;
    const int n = ntile * 8 + (ln >> 2);
    const int k0 = ks * 16 + 2 * (ln & 3);
    const float w00 = W2[n*H + k0],     w01 = W2[n*H + k0 + 1];
    const float w10 = W2[n*H + k0 + 8], w11 = W2[n*H + k0 + 9];
    const __nv_bfloat16 a00 = __float2bfloat16(w00), a01 = __float2bfloat16(w01);
    const __nv_bfloat16 a10 = __float2bfloat16(w10), a11 = __float2bfloat16(w11);
    uint2 hi, lo;
    hi.x = (uint32_t)__bfloat16_as_ushort(a00) | ((uint32_t)__bfloat16_as_ushort(a01) << 16);
    hi.y = (uint32_t)__bfloat16_as_ushort(a10) | ((uint32_t)__bfloat16_as_ushort(a11) << 16);
    lo.x = pkbf(w00 - __bfloat162float(a00), w01 - __bfloat162float(a01));
    lo.y = pkbf(w10 - __bfloat162float(a10), w11 - __bfloat162float(a11));
    char* base = (char*)g_W2f + ntile*4096 + ks*256 + ln*8;
    *(uint2*)base        = hi;
    *(uint2*)(base + 2048) = lo;
}

__global__ void __launch_bounds__(NTH, 1)
rnnode_mma(const float* __restrict__ x, const float* __restrict__ span,
           const float* __restrict__ W_emb, const float* __restrict__ b_emb,
           const float* __restrict__ W_ih, const float* __restrict__ b_ih,
           const float* __restrict__ W_hh, const float* __restrict__ b_hh,
           const float* __restrict__ W1, const float* __restrict__ b1,
           const float* __restrict__ W2, const float* __restrict__ b2,
           const float* __restrict__ W_out, const float* __restrict__ b_out,
           float* __restrict__ out) {
    extern __shared__ char smc[];
    const uint32_t smb = smem_u32(smc);
    const int tid = threadIdx.x;
    const int lane = tid & 31, wid = tid >> 5;
    const int bb0 = blockIdx.x * NB;
    float* xs = (float*)(smc + SM_XS);

    // ---- fill weight fragment buffers (Whh, W1, P) in B-fragment order ----
#pragma unroll 1
    for (int m = 0; m < 3; m++) {
        const float* W = (m == 0) ? W_hh : (m == 1) ? W1 : g_P;
        char* wf = smc + (m == 0 ? SM_WF0 : m == 1 ? SM_WF1 : SM_WFP);
        for (int fi = tid; fi < 4096; fi += NTH) {
            const int ntile = fi >> 8, ks = (fi >> 5) & 7, ln = fi & 31;
            const int n = ntile * 8 + (ln >> 2);
            const int k0 = ks * 16 + 2 * (ln & 3);
            const float w00 = W[n*H + k0],     w01 = W[n*H + k0 + 1];
            const float w10 = W[n*H + k0 + 8], w11 = W[n*H + k0 + 9];
            const __nv_bfloat16 a00 = __float2bfloat16(w00), a01 = __float2bfloat16(w01);
            const __nv_bfloat16 a10 = __float2bfloat16(w10), a11 = __float2bfloat16(w11);
            uint2 hi, lo;
            hi.x = (uint32_t)__bfloat16_as_ushort(a00) | ((uint32_t)__bfloat16_as_ushort(a01) << 16);
            hi.y = (uint32_t)__bfloat16_as_ushort(a10) | ((uint32_t)__bfloat16_as_ushort(a11) << 16);
            lo.x = pkbf(w00 - __bfloat162float(a00), w01 - __bfloat162float(a01));
            lo.y = pkbf(w10 - __bfloat162float(a10), w11 - __bfloat162float(a11));
            const uint32_t base = ntile*4096 + ks*256 + ln*8;
            *(uint2*)(wf + base)        = hi;
            *(uint2*)(wf + base + 2048) = lo;
        }
    }

    // ---- per-thread fragment geometry ----
    const int g0 = lane >> 2, tq = lane & 3;
    const int r0 = g0, r1 = g0 + 8;
    const int cb0 = wid * 16 + 2 * tq;
    const uint32_t o00 = (uint32_t)(r0 * ROWB + cb0 * 2);
    const uint32_t o10 = (uint32_t)(r1 * ROWB + cb0 * 2);
    const uint32_t arow = (uint32_t)((((lane >> 3) & 1) * 8) + (lane & 7));
    const uint32_t aoff = arow * ROWB + (((lane >> 4) & 1) * 8) * 2;
    const uint32_t boff = (uint32_t)((wid * 2) * 4096 + lane * 8);

    // ---- per-col constants {cb0, cb0+1, cb0+8, cb0+9} ----
    float cv[4], ccst[4], b1c[4], b2c[4], c1c[4];
#pragma unroll
    for (int q = 0; q < 4; q++) {
        const int col = cb0 + (q >> 1) * 8 + (q & 1);
        float vv = 0.0f, cc = 0.0f;
        for (int d = 0; d < D_IN; d++) {
            const float w = W_ih[col * D_IN + d];
            vv = fmaf(w, W_emb[d], vv);
            cc = fmaf(w, b_emb[d], cc);
        }
        cv[q] = vv;
        ccst[q] = cc + b_ih[col] + b_hh[col];
        b1c[q] = b1[col];
        b2c[q] = b2[col];
        float c1v = 0.0f;
        for (int k = 0; k < H; k++) c1v = fmaf(b2[k], W1[col * H + k], c1v);
        c1c[q] = c1v;
    }
    __syncthreads();

    const uint32_t abu[2] = {smb + SM_AB0, smb + SM_AB1};
    char* abp[2] = {smc + SM_AB0, smc + SM_AB1};
    const char* wf0 = smc + SM_WF0;
    const char* wf1 = smc + SM_WF1;
    const char* wfp = smc + SM_WFP;
    const char* gw2 = (const char*)g_W2f;

    float h[8], z1[8], u1[8], u2[8], u3[8], g[8];
#pragma unroll
    for (int i = 0; i < 8; i++) h[i] = 0.0f;
    int p = 0;

#define QSEL(i) (((i) >> 2) * 2 + ((i) & 1))
#define RSEL(i) ((((i) >> 1) & 1))

#pragma unroll 1
    for (int t = 0; t < NSTEPS; t++) {
        const float dt   = __ldg(span + t + 1) - __ldg(span + t);
        const float dt3  = dt * (1.0f / 3.0f);
        const float dt23 = 2.0f * dt3;
        const float dt8  = dt * 0.125f;

        if (tid < NB) xs[tid] = x[(size_t)(bb0 + tid) * T_SZ + t];

        // G1: h = tanh(x*v + c + h@Whh^T)
        stage8(abp[p], h, o00, o10);
        __syncthreads();
        gemm48s(abu[p], aoff, wf0, boff, g);
        p ^= 1;
        {
            const float xr[2] = {xs[r0], xs[r1]};
#pragma unroll
            for (int i = 0; i < 8; i++) {
                const int q = QSEL(i);
                h[i] = tanhf(g[i] + fmaf(xr[RSEL(i)], cv[q], ccst[q]));
            }
        }
        // G2: z1 = h@W1^T + b1; u1 = silu(z1)
        stage8(abp[p], h, o00, o10);
        __syncthreads();
        gemm48s(abu[p], aoff, wf1, boff, g);
        p ^= 1;
#pragma unroll
        for (int i = 0; i < 8; i++) {
            z1[i] = g[i] + b1c[QSEL(i)];
            u1[i] = silu_f(z1[i]);
        }
        // G3: u2 = silu(z1 + dt/3*(u1@P^T + c1))
        stage8(abp[p], u1, o00, o10);
        __syncthreads();
        gemm48s(abu[p], aoff, wfp, boff, g);
        p ^= 1;
#pragma unroll
        for (int i = 0; i < 8; i++) {
            u2[i] = silu_f(fmaf(dt3, g[i] + c1c[QSEL(i)], z1[i]));
            g[i] = fmaf(-(1.0f / 3.0f), u1[i], u2[i]);
        }
        // G4: u3 = silu(z1 + dt*((u2-u1/3)@P^T) + 2dt/3*c1)
        stage8(abp[p], g, o00, o10);
        __syncthreads();
        gemm48s(abu[p], aoff, wfp, boff, g);
        p ^= 1;
#pragma unroll
        for (int i = 0; i < 8; i++) {
            u3[i] = silu_f(fmaf(dt, g[i], fmaf(dt23, c1c[QSEL(i)], z1[i])));
            g[i] = u1[i] - u2[i] + u3[i];
        }
        // G5: u4 = silu(z1 + dt*((u1-u2+u3)@P^T + c1)); g4 = u1+3(u2+u3)+u4
        stage8(abp[p], g, o00, o10);
        __syncthreads();
        gemm48s(abu[p], aoff, wfp, boff, g);
        p ^= 1;
#pragma unroll
        for (int i = 0; i < 8; i++) {
            const float u4 = silu_f(fmaf(dt, g[i] + c1c[QSEL(i)], z1[i]));
            g[i] = fmaf(3.0f, u2[i] + u3[i], u1[i] + u4);
        }
        // G6: h += dt/8*(g4@W2^T) + dt*b2   (B streamed from L2)
        stage8(abp[p], g, o00, o10);
        __syncthreads();
        gemm48g(abu[p], aoff, gw2, boff, g);
        p ^= 1;
#pragma unroll
        for (int i = 0; i < 8; i++)
            h[i] = fmaf(dt8, g[i], fmaf(dt, b2c[QSEL(i)], h[i]));
    }

    // ---- epilogue: out = h @ W_out^T + b_out ----
    __syncthreads();
    float* hb = (float*)smc;  // reuse WF0 region: [16][128] fp32
#pragma unroll
    for (int ntl = 0; ntl < 2; ntl++) {
        const int c = cb0 + ntl * 8;
        hb[r0 * H + c]     = h[ntl*4+0];
        hb[r0 * H + c + 1] = h[ntl*4+1];
        hb[r1 * H + c]     = h[ntl*4+2];
        hb[r1 * H + c + 1] = h[ntl*4+3];
    }
    __syncthreads();
    {
        const int j = tid & 63, q = tid >> 6;
        float o[4];
        const float bo = __ldg(b_out + j);
#pragma unroll
        for (int n = 0; n < 4; n++) o[n] = bo;
        const float* Wo = W_out + j * H;
#pragma unroll 4
        for (int k = 0; k < H; k++) {
            const float wv = __ldg(Wo + k);
            const float* ar = hb + (q * 4) * H + k;
#pragma unroll
            for (int n = 0; n < 4; n++) o[n] = fmaf(ar[n * H], wv, o[n]);
        }
#pragma unroll
        for (int n = 0; n < 4; n++)
            out[(size_t)(bb0 + q * 4 + n) * D_OUT + j] = o[n];
    }
}

extern "C" void kernel_launch(void* const* d_in, const int* in_sizes, int n_in,
                              void* d_out, int out_size) {
    const float* x     = (const float*)d_in[0];
    const float* span  = (const float*)d_in[1];
    const float* W_emb = (const float*)d_in[2];
    const float* b_emb = (const float*)d_in[3];
    const float* W_ih  = (const float*)d_in[4];
    const float* b_ih  = (const float*)d_in[5];
    const float* W_hh  = (const float*)d_in[6];
    const float* b_hh  = (const float*)d_in[7];
    const float* W1    = (const float*)d_in[8];
    const float* b1    = (const float*)d_in[9];
    const float* W2    = (const float*)d_in[10];
    const float* b2    = (const float*)d_in[11];
    const float* W_out = (const float*)d_in[12];
    const float* b_out = (const float*)d_in[13];
    float* out = (float*)d_out;

    prep_p<<<H, H>>>(W1, W2);
    prep_frag<<<16, 256>>>(W2);
    cudaFuncSetAttribute(rnnode_mma, cudaFuncAttributeMaxDynamicSharedMemorySize,
                         SMEM_BYTES);
    rnnode_mma<<<B_SZ / NB, NTH, SMEM_BYTES>>>(
        x, span, W_emb, b_emb, W_ih, b_ih, W_hh, b_hh,
        W1, b1, W2, b2, W_out, b_out, out);
}

// round 12
// speedup vs baseline: 3.5580x; 1.0226x over previous
#include <cuda_runtime.h>
#include <cuda_bf16.h>
#include <stdint.h>
#include <math.h>

#define B_SZ 2048
#define T_SZ 512
#define D_IN 64
#define H    128
#define D_OUT 64
#define NB   16
#define NTH  256
#define NSTEPS (T_SZ-1)
#define ROWB 528   // activation buffer row stride in bytes (264 bf16)

// SMEM byte offsets
#define SM_WF1 0        // W1 fragments (64KB)
#define SM_WFP 65536    // P fragments
#define SM_WFQ 131072   // Q fragments
#define SM_AB0 196608   // activation ping  [16][264] bf16
#define SM_AB1 205056   // activation pong
#define SM_XS  213504   // 16 floats
#define SMEM_BYTES 213568

__device__ float g_P[H * H];               // P = W1 @ W2   (row-major [j][k])
__device__ float g_Q[H * H];               // Q = Whh @ W2  (row-major [j][k])
__device__ unsigned long long g_W2f[8192]; // W2 fragments (64KB)
__device__ unsigned long long g_Whf[8192]; // Whh fragments (64KB)

__device__ __forceinline__ uint32_t smem_u32(const void* p) {
    uint32_t a;
    asm("{ .reg .u64 t; cvta.to.shared.u64 t, %1; cvt.u32.u64 %0, t; }" : "=r"(a) : "l"(p));
    return a;
}
__device__ __forceinline__ uint32_t pkbf(float a, float b) {
    __nv_bfloat16 ha = __float2bfloat16(a), hb = __float2bfloat16(b);
    return (uint32_t)__bfloat16_as_ushort(ha) | ((uint32_t)__bfloat16_as_ushort(hb) << 16);
}
__device__ __forceinline__ void ldsm4(uint32_t& r0, uint32_t& r1, uint32_t& r2,
                                      uint32_t& r3, uint32_t addr) {
    asm volatile("ldmatrix.sync.aligned.m8n8.x4.shared.b16 {%0,%1,%2,%3}, [%4];"
                 : "=r"(r0), "=r"(r1), "=r"(r2), "=r"(r3) : "r"(addr));
}
__device__ __forceinline__ void mma_bf16(float* d, uint32_t a0, uint32_t a1,
                                         uint32_t a2, uint32_t a3,
                                         uint32_t b0, uint32_t b1) {
    asm volatile("mma.sync.aligned.m16n8k16.row.col.f32.bf16.bf16.f32 "
                 "{%0,%1,%2,%3}, {%4,%5,%6,%7}, {%8,%9}, {%0,%1,%2,%3};"
                 : "+f"(d[0]), "+f"(d[1]), "+f"(d[2]), "+f"(d[3])
                 : "r"(a0), "r"(a1), "r"(a2), "r"(a3), "r"(b0), "r"(b1));
}
__device__ __forceinline__ float silu_f(float v) {
    return __fdividef(v, 1.0f + __expf(-v));
}
__device__ __forceinline__ float tanh_f(float v) {
    return 1.0f - __fdividef(2.0f, __expf(2.0f * v) + 1.0f);
}

// Stage 8 fragment values into activation buffer as bf16 hi (+0) / lo (+256B).
__device__ __forceinline__ void stage8(char* ab, const float* v,
                                       uint32_t o00, uint32_t o10) {
#pragma unroll
    for (int ntl = 0; ntl < 2; ntl++) {
        const float d0 = v[ntl*4+0], d1 = v[ntl*4+1];
        const float d2 = v[ntl*4+2], d3 = v[ntl*4+3];
        const uint32_t oa = o00 + ntl*16, ob = o10 + ntl*16;
        const __nv_bfloat16 h0 = __float2bfloat16(d0), h1 = __float2bfloat16(d1);
        const __nv_bfloat16 h2 = __float2bfloat16(d2), h3 = __float2bfloat16(d3);
        *(uint32_t*)(ab + oa) = (uint32_t)__bfloat16_as_ushort(h0) |
                                ((uint32_t)__bfloat16_as_ushort(h1) << 16);
        *(uint32_t*)(ab + ob) = (uint32_t)__bfloat16_as_ushort(h2) |
                                ((uint32_t)__bfloat16_as_ushort(h3) << 16);
        *(uint32_t*)(ab + oa + 256) = pkbf(d0 - __bfloat162float(h0),
                                           d1 - __bfloat162float(h1));
        *(uint32_t*)(ab + ob + 256) = pkbf(d2 - __bfloat162float(h2),
                                           d3 - __bfloat162float(h3));
    }
}

// GEMM, B from SMEM, 3 accumulator groups (term-split -> 8-deep HMMA chains).
__device__ __forceinline__ void gemm48s(uint32_t ab_u32, uint32_t aoff,
                                        const char* wf, uint32_t boff,
                                        float* dout) {
    float a0[8], a1[8], a2[8];
#pragma unroll
    for (int i = 0; i < 8; i++) { a0[i] = 0.f; a1[i] = 0.f; a2[i] = 0.f; }
#pragma unroll
    for (int s = 0; s < 8; s++) {
        uint32_t ah0, ah1, ah2, ah3, al0, al1, al2, al3;
        const uint32_t aa = ab_u32 + aoff + s*32;
        ldsm4(ah0, ah1, ah2, ah3, aa);
        ldsm4(al0, al1, al2, al3, aa + 256);
#pragma unroll
        for (int ntl = 0; ntl < 2; ntl++) {
            const char* bb = wf + boff + ntl*4096 + s*256;
            const uint2 bh = *(const uint2*)bb;
            const uint2 bl = *(const uint2*)(bb + 2048);
            mma_bf16(a0 + ntl*4, ah0, ah1, ah2, ah3, bh.x, bh.y);
            mma_bf16(a1 + ntl*4, ah0, ah1, ah2, ah3, bl.x, bl.y);
            mma_bf16(a2 + ntl*4, al0, al1, al2, al3, bh.x, bh.y);
        }
    }
#pragma unroll
    for (int i = 0; i < 8; i++) dout[i] = a0[i] + a1[i] + a2[i];
}

// GEMM, B streamed from global (L2). All 32 B-frag loads issued up front.
__device__ __forceinline__ void gemm48g(uint32_t ab_u32, uint32_t aoff,
                                        const char* gw, uint32_t boff,
                                        float* dout) {
    uint2 BH[16], BL[16];
#pragma unroll
    for (int s = 0; s < 8; s++) {
#pragma unroll
        for (int ntl = 0; ntl < 2; ntl++) {
            const char* bb = gw + boff + ntl*4096 + s*256;
            BH[s*2+ntl] = __ldg((const uint2*)bb);
            BL[s*2+ntl] = __ldg((const uint2*)(bb + 2048));
        }
    }
    float a0[8], a1[8], a2[8];
#pragma unroll
    for (int i = 0; i < 8; i++) { a0[i] = 0.f; a1[i] = 0.f; a2[i] = 0.f; }
#pragma unroll
    for (int s = 0; s < 8; s++) {
        uint32_t ah0, ah1, ah2, ah3, al0, al1, al2, al3;
        const uint32_t aa = ab_u32 + aoff + s*32;
        ldsm4(ah0, ah1, ah2, ah3, aa);
        ldsm4(al0, al1, al2, al3, aa + 256);
#pragma unroll
        for (int ntl = 0; ntl < 2; ntl++) {
            const uint2 bh = BH[s*2+ntl];
            const uint2 bl = BL[s*2+ntl];
            mma_bf16(a0 + ntl*4, ah0, ah1, ah2, ah3, bh.x, bh.y);
            mma_bf16(a1 + ntl*4, ah0, ah1, ah2, ah3, bl.x, bl.y);
            mma_bf16(a2 + ntl*4, al0, al1, al2, al3, bh.x, bh.y);
        }
    }
#pragma unroll
    for (int i = 0; i < 8; i++) dout[i] = a0[i] + a1[i] + a2[i];
}

// ---- prep kernels ----
// out[j][k] = sum_m A[j][m] * B[m][k]   (out = g_P if sel==0 else g_Q)
__global__ void prep_mm(const float* __restrict__ A, const float* __restrict__ B,
                        int sel) {
    __shared__ float arow[H];
    const int j = blockIdx.x, k = threadIdx.x;
    arow[k] = A[j * H + k];
    __syncthreads();
    float s = 0.0f;
#pragma unroll 8
    for (int m = 0; m < H; m++) s = fmaf(arow[m], B[m * H + k], s);
    (sel ? g_Q : g_P)[j * H + k] = s;
}

// Fragment a weight matrix into global fragment buffer (sel: 0=W2f, 1=Whf).
__global__ void prep_frag(const float* __restrict__ W, int sel) {
    const int fi = blockIdx.x * blockDim.x + threadIdx.x;  // 0..4095
    const int ntile = fi >> 8, ks = (fi >> 5) & 7, ln = fi & 31;
    const int n = ntile * 8 + (ln >> 2);
    const int k0 = ks * 16 + 2 * (ln & 3);
    const float w00 = W[n*H + k0],     w01 = W[n*H + k0 + 1];
    const float w10 = W[n*H + k0 + 8], w11 = W[n*H + k0 + 9];
    const __nv_bfloat16 a00 = __float2bfloat16(w00), a01 = __float2bfloat16(w01);
    const __nv_bfloat16 a10 = __float2bfloat16(w10), a11 = __float2bfloat16(w11);
    uint2 hi, lo;
    hi.x = (uint32_t)__bfloat16_as_ushort(a00) | ((uint32_t)__bfloat16_as_ushort(a01) << 16);
    hi.y = (uint32_t)__bfloat16_as_ushort(a10) | ((uint32_t)__bfloat16_as_ushort(a11) << 16);
    lo.x = pkbf(w00 - __bfloat162float(a00), w01 - __bfloat162float(a01));
    lo.y = pkbf(w10 - __bfloat162float(a10), w11 - __bfloat162float(a11));
    char* base = (char*)(sel ? g_Whf : g_W2f) + ntile*4096 + ks*256 + ln*8;
    *(uint2*)base          = hi;
    *(uint2*)(base + 2048) = lo;
}

__global__ void __launch_bounds__(NTH, 1)
rnnode_mma(const float* __restrict__ x, const float* __restrict__ span,
           const float* __restrict__ W_emb, const float* __restrict__ b_emb,
           const float* __restrict__ W_ih, const float* __restrict__ b_ih,
           const float* __restrict__ W_hh, const float* __restrict__ b_hh,
           const float* __restrict__ W1, const float* __restrict__ b1,
           const float* __restrict__ W2, const float* __restrict__ b2,
           const float* __restrict__ W_out, const float* __restrict__ b_out,
           float* __restrict__ out) {
    extern __shared__ char smc[];
    const uint32_t smb = smem_u32(smc);
    const int tid = threadIdx.x;
    const int lane = tid & 31, wid = tid >> 5;
    const int bb0 = blockIdx.x * NB;
    float* xs = (float*)(smc + SM_XS);

    // ---- fill SMEM weight fragment buffers (W1, P, Q) in B-fragment order ----
#pragma unroll 1
    for (int m = 0; m < 3; m++) {
        const float* W = (m == 0) ? W1 : (m == 1) ? g_P : g_Q;
        char* wf = smc + (m == 0 ? SM_WF1 : m == 1 ? SM_WFP : SM_WFQ);
        for (int fi = tid; fi < 4096; fi += NTH) {
            const int ntile = fi >> 8, ks = (fi >> 5) & 7, ln = fi & 31;
            const int n = ntile * 8 + (ln >> 2);
            const int k0 = ks * 16 + 2 * (ln & 3);
            const float w00 = W[n*H + k0],     w01 = W[n*H + k0 + 1];
            const float w10 = W[n*H + k0 + 8], w11 = W[n*H + k0 + 9];
            const __nv_bfloat16 a00 = __float2bfloat16(w00), a01 = __float2bfloat16(w01);
            const __nv_bfloat16 a10 = __float2bfloat16(w10), a11 = __float2bfloat16(w11);
            uint2 hi, lo;
            hi.x = (uint32_t)__bfloat16_as_ushort(a00) | ((uint32_t)__bfloat16_as_ushort(a01) << 16);
            hi.y = (uint32_t)__bfloat16_as_ushort(a10) | ((uint32_t)__bfloat16_as_ushort(a11) << 16);
            lo.x = pkbf(w00 - __bfloat162float(a00), w01 - __bfloat162float(a01));
            lo.y = pkbf(w10 - __bfloat162float(a10), w11 - __bfloat162float(a11));
            const uint32_t base = ntile*4096 + ks*256 + ln*8;
            *(uint2*)(wf + base)        = hi;
            *(uint2*)(wf + base + 2048) = lo;
        }
    }

    // ---- per-thread fragment geometry ----
    const int g0 = lane >> 2, tq = lane & 3;
    const int r0 = g0, r1 = g0 + 8;
    const int cb0 = wid * 16 + 2 * tq;
    const uint32_t o00 = (uint32_t)(r0 * ROWB + cb0 * 2);
    const uint32_t o10 = (uint32_t)(r1 * ROWB + cb0 * 2);
    const uint32_t arow = (uint32_t)((((lane >> 3) & 1) * 8) + (lane & 7));
    const uint32_t aoff = arow * ROWB + (((lane >> 4) & 1) * 8) * 2;
    const uint32_t boff = (uint32_t)((wid * 2) * 4096 + lane * 8);

    // ---- per-col constants for cols {cb0, cb0+1, cb0+8, cb0+9} ----
    float cv[4], ccst[4], b1c[4], b2c[4], c1c[4], cwc[4];
#pragma unroll
    for (int q = 0; q < 4; q++) {
        const int col = cb0 + (q >> 1) * 8 + (q & 1);
        float vv = 0.0f, cc = 0.0f;
        for (int d = 0; d < D_IN; d++) {
            const float w = W_ih[col * D_IN + d];
            vv = fmaf(w, W_emb[d], vv);
            cc = fmaf(w, b_emb[d], cc);
        }
        cv[q] = vv;
        ccst[q] = cc + b_ih[col] + b_hh[col];
        b1c[q] = b1[col];
        b2c[q] = b2[col];
        float c1v = 0.0f, cwv = 0.0f;
        for (int k = 0; k < H; k++) {
            c1v = fmaf(b2[k], W1[col * H + k], c1v);
            cwv = fmaf(b2[k], W_hh[col * H + k], cwv);
        }
        c1c[q] = c1v;   // b2 @ W1^T
        cwc[q] = cwv;   // b2 @ Whh^T
    }
    // x for t=0
    if (tid < NB) xs[tid] = x[(size_t)(bb0 + tid) * T_SZ];
    __syncthreads();

    const uint32_t abu[2] = {smb + SM_AB0, smb + SM_AB1};
    char* abp[2] = {smc + SM_AB0, smc + SM_AB1};
    const char* wf1 = smc + SM_WF1;
    const char* wfp = smc + SM_WFP;
    const char* wfq = smc + SM_WFQ;
    const char* gw2 = (const char*)g_W2f;
    const char* gwh = (const char*)g_Whf;

#define QSEL(i) (((i) >> 2) * 2 + ((i) & 1))
#define RSEL(i) ((((i) >> 1) & 1))

    // htan_0 = tanh(x_0*v + c)   (s_0 = 0 since h_0 = 0)
    float htan[8], sW[8], z1[8], u1[8], u2[8], u3[8], g[8];
    {
        const float xr[2] = {xs[r0], xs[r1]};
#pragma unroll
        for (int i = 0; i < 8; i++) {
            const int q = QSEL(i);
            htan[i] = tanh_f(fmaf(xr[RSEL(i)], cv[q], ccst[q]));
        }
    }
    int p = 0;
    float dtL = 1.0f;

#pragma unroll 1
    for (int t = 0; t < NSTEPS; t++) {
        const float dt   = __ldg(span + t + 1) - __ldg(span + t);
        const float dt3  = dt * (1.0f / 3.0f);
        const float dt23 = 2.0f * dt3;
        const float dt8  = dt * 0.125f;
        dtL = dt;

        // L1: stage htan; Whh-GEMM (L2) -> sW ; W1-GEMM (SMEM) -> z1
        stage8(abp[p], htan, o00, o10);
        if (tid < NB) xs[tid] = x[(size_t)(bb0 + tid) * T_SZ + (t + 1)];
        __syncthreads();
        gemm48g(abu[p], aoff, gwh, boff, sW);
        gemm48s(abu[p], aoff, wf1, boff, g);
        p ^= 1;
#pragma unroll
        for (int i = 0; i < 8; i++) {
            z1[i] = g[i] + b1c[QSEL(i)];
            u1[i] = silu_f(z1[i]);
        }
        // L2: u2 = silu(z1 + dt/3*(u1@P^T + c1))
        stage8(abp[p], u1, o00, o10);
        __syncthreads();
        gemm48s(abu[p], aoff, wfp, boff, g);
        p ^= 1;
#pragma unroll
        for (int i = 0; i < 8; i++) {
            u2[i] = silu_f(fmaf(dt3, g[i] + c1c[QSEL(i)], z1[i]));
            g[i] = fmaf(-(1.0f / 3.0f), u1[i], u2[i]);
        }
        // L3: u3 = silu(z1 + dt*((u2-u1/3)@P^T) + 2dt/3*c1)
        stage8(abp[p], g, o00, o10);
        __syncthreads();
        gemm48s(abu[p], aoff, wfp, boff, g);
        p ^= 1;
#pragma unroll
        for (int i = 0; i < 8; i++) {
            u3[i] = silu_f(fmaf(dt, g[i], fmaf(dt23, c1c[QSEL(i)], z1[i])));
            g[i] = u1[i] - u2[i] + u3[i];
        }
        // L4: u4 = silu(z1 + dt*((u1-u2+u3)@P^T + c1)); g4 = u1+3(u2+u3)+u4
        stage8(abp[p], g, o00, o10);
        __syncthreads();
        gemm48s(abu[p], aoff, wfp, boff, g);
        p ^= 1;
#pragma unroll
        for (int i = 0; i < 8; i++) {
            const float u4 = silu_f(fmaf(dt, g[i] + c1c[QSEL(i)], z1[i]));
            g[i] = fmaf(3.0f, u2[i] + u3[i], u1[i] + u4);
        }
        // L5 (skip on last step): s+ = sW + dt/8*(g4@Q^T) + dt*cw ;
        //                         htan+ = tanh(x+*v + c + s+)
        stage8(abp[p], g, o00, o10);
        __syncthreads();
        if (t + 1 < NSTEPS) {
            gemm48s(abu[p], aoff, wfq, boff, g);
            p ^= 1;
            const float xr[2] = {xs[r0], xs[r1]};
#pragma unroll
            for (int i = 0; i < 8; i++) {
                const int q = QSEL(i);
                const float s = fmaf(dt8, g[i], fmaf(dt, cwc[q], sW[i]));
                htan[i] = tanh_f(fmaf(xr[RSEL(i)], cv[q], ccst[q]) + s);
            }
        }
    }

    // ---- final h = htan + dt/8*(g4@W2^T) + dt*b2 (g4 staged in buf p) ----
    {
        gemm48g(abu[p], aoff, gw2, boff, g);
        const float dt8L = dtL * 0.125f;
#pragma unroll
        for (int i = 0; i < 8; i++)
            htan[i] = fmaf(dt8L, g[i], fmaf(dtL, b2c[QSEL(i)], htan[i]));
    }

    // ---- epilogue: out = h @ W_out^T + b_out ----
    __syncthreads();
    float* hb = (float*)smc;  // reuse WF1 region: [16][128] fp32
#pragma unroll
    for (int ntl = 0; ntl < 2; ntl++) {
        const int c = cb0 + ntl * 8;
        hb[r0 * H + c]     = htan[ntl*4+0];
        hb[r0 * H + c + 1] = htan[ntl*4+1];
        hb[r1 * H + c]     = htan[ntl*4+2];
        hb[r1 * H + c + 1] = htan[ntl*4+3];
    }
    __syncthreads();
    {
        const int j = tid & 63, q = tid >> 6;
        float o[4];
        const float bo = __ldg(b_out + j);
#pragma unroll
        for (int n = 0; n < 4; n++) o[n] = bo;
        const float* Wo = W_out + j * H;
#pragma unroll 4
        for (int k = 0; k < H; k++) {
            const float wv = __ldg(Wo + k);
            const float* ar = hb + (q * 4) * H + k;
#pragma unroll
            for (int n = 0; n < 4; n++) o[n] = fmaf(ar[n * H], wv, o[n]);
        }
#pragma unroll
        for (int n = 0; n < 4; n++)
            out[(size_t)(bb0 + q * 4 + n) * D_OUT + j] = o[n];
    }
}

extern "C" void kernel_launch(void* const* d_in, const int* in_sizes, int n_in,
                              void* d_out, int out_size) {
    const float* x     = (const float*)d_in[0];
    const float* span  = (const float*)d_in[1];
    const float* W_emb = (const float*)d_in[2];
    const float* b_emb = (const float*)d_in[3];
    const float* W_ih  = (const float*)d_in[4];
    const float* b_ih  = (const float*)d_in[5];
    const float* W_hh  = (const float*)d_in[6];
    const float* b_hh  = (const float*)d_in[7];
    const float* W1    = (const float*)d_in[8];
    const float* b1    = (const float*)d_in[9];
    const float* W2    = (const float*)d_in[10];
    const float* b2    = (const float*)d_in[11];
    const float* W_out = (const float*)d_in[12];
    const float* b_out = (const float*)d_in[13];
    float* out = (float*)d_out;

    prep_mm<<<H, H>>>(W1, W2, 0);     // P = W1 @ W2
    prep_mm<<<H, H>>>(W_hh, W2, 1);   // Q = Whh @ W2
    prep_frag<<<16, 256>>>(W2, 0);
    prep_frag<<<16, 256>>>(W_hh, 1);
    cudaFuncSetAttribute(rnnode_mma, cudaFuncAttributeMaxDynamicSharedMemorySize,
                         SMEM_BYTES);
    rnnode_mma<<<B_SZ / NB, NTH, SMEM_BYTES>>>(
        x, span, W_emb, b_emb, W_ih, b_ih, W_hh, b_hh,
        W1, b1, W2, b2, W_out, b_out, out);
}

// round 13
// speedup vs baseline: 3.9540x; 1.1113x over previous
#include <cuda_runtime.h>
#include <cuda_bf16.h>
#include <stdint.h>
#include <math.h>

#define B_SZ 2048
#define T_SZ 512
#define D_IN 64
#define H    128
#define D_OUT 64
#define NB   16
#define NTH  256
#define NSTEPS (T_SZ-1)
#define ROWB 528   // activation buffer row stride in bytes (264 bf16)

// SMEM byte offsets
#define SM_WF1 0        // W1 fragments (64KB)
#define SM_WFP 65536    // P fragments
#define SM_WFQ 131072   // Q fragments
#define SM_AB0 196608   // activation ping  [16][264] bf16
#define SM_AB1 205056   // activation pong
#define SM_XS  213504   // 16 floats
#define SMEM_BYTES 213568

__device__ float g_P[H * H];               // P = W1 @ W2   (row-major [j][k])
__device__ float g_Q[H * H];               // Q = Whh @ W2  (row-major [j][k])
__device__ unsigned long long g_W2f[8192]; // W2 fragments (64KB)
__device__ unsigned long long g_Whf[8192]; // Whh fragments (64KB)

__device__ __forceinline__ uint32_t smem_u32(const void* p) {
    uint32_t a;
    asm("{ .reg .u64 t; cvta.to.shared.u64 t, %1; cvt.u32.u64 %0, t; }" : "=r"(a) : "l"(p));
    return a;
}
__device__ __forceinline__ uint32_t pkbf(float a, float b) {
    __nv_bfloat16 ha = __float2bfloat16(a), hb = __float2bfloat16(b);
    return (uint32_t)__bfloat16_as_ushort(ha) | ((uint32_t)__bfloat16_as_ushort(hb) << 16);
}
__device__ __forceinline__ void ldsm4(uint32_t& r0, uint32_t& r1, uint32_t& r2,
                                      uint32_t& r3, uint32_t addr) {
    asm volatile("ldmatrix.sync.aligned.m8n8.x4.shared.b16 {%0,%1,%2,%3}, [%4];"
                 : "=r"(r0), "=r"(r1), "=r"(r2), "=r"(r3) : "r"(addr));
}
__device__ __forceinline__ void mma_bf16(float* d, uint32_t a0, uint32_t a1,
                                         uint32_t a2, uint32_t a3,
                                         uint32_t b0, uint32_t b1) {
    asm volatile("mma.sync.aligned.m16n8k16.row.col.f32.bf16.bf16.f32 "
                 "{%0,%1,%2,%3}, {%4,%5,%6,%7}, {%8,%9}, {%0,%1,%2,%3};"
                 : "+f"(d[0]), "+f"(d[1]), "+f"(d[2]), "+f"(d[3])
                 : "r"(a0), "r"(a1), "r"(a2), "r"(a3), "r"(b0), "r"(b1));
}
__device__ __forceinline__ float tanh_hw(float v) {
    float t;
    asm("tanh.approx.f32 %0, %1;" : "=f"(t) : "f"(v));
    return t;
}
__device__ __forceinline__ float silu_f(float v) {
    const float hv = 0.5f * v;
    return fmaf(hv, tanh_hw(hv), hv);
}

// Pack (d0,d1) -> bf16x2 hi word + bf16x2 lo-residual word.
__device__ __forceinline__ void pack_hl(float d0, float d1, uint32_t& hp, uint32_t& lp) {
    asm("cvt.rn.bf16x2.f32 %0, %1, %2;" : "=r"(hp) : "f"(d1), "f"(d0));
    const float f0 = __uint_as_float(hp << 16);
    const float f1 = __uint_as_float(hp & 0xFFFF0000u);
    asm("cvt.rn.bf16x2.f32 %0, %1, %2;" : "=r"(lp) : "f"(d1 - f1), "f"(d0 - f0));
}

// Stage 8 fragment values into activation buffer as bf16 hi (+0) / lo (+256B).
__device__ __forceinline__ void stage8(char* ab, const float* v,
                                       uint32_t o00, uint32_t o10) {
#pragma unroll
    for (int ntl = 0; ntl < 2; ntl++) {
        const uint32_t oa = o00 + ntl*16, ob = o10 + ntl*16;
        uint32_t hp, lp;
        pack_hl(v[ntl*4+0], v[ntl*4+1], hp, lp);
        *(uint32_t*)(ab + oa) = hp;
        *(uint32_t*)(ab + oa + 256) = lp;
        pack_hl(v[ntl*4+2], v[ntl*4+3], hp, lp);
        *(uint32_t*)(ab + ob) = hp;
        *(uint32_t*)(ab + ob + 256) = lp;
    }
}

// GEMM, B from SMEM, 3 accumulator groups (term-split -> 8-deep HMMA chains).
__device__ __forceinline__ void gemm48s(uint32_t ab_u32, uint32_t aoff,
                                        const char* wf, uint32_t boff,
                                        float* dout) {
    float a0[8], a1[8], a2[8];
#pragma unroll
    for (int i = 0; i < 8; i++) { a0[i] = 0.f; a1[i] = 0.f; a2[i] = 0.f; }
#pragma unroll
    for (int s = 0; s < 8; s++) {
        uint32_t ah0, ah1, ah2, ah3, al0, al1, al2, al3;
        const uint32_t aa = ab_u32 + aoff + s*32;
        ldsm4(ah0, ah1, ah2, ah3, aa);
        ldsm4(al0, al1, al2, al3, aa + 256);
#pragma unroll
        for (int ntl = 0; ntl < 2; ntl++) {
            const char* bb = wf + boff + ntl*4096 + s*256;
            const uint2 bh = *(const uint2*)bb;
            const uint2 bl = *(const uint2*)(bb + 2048);
            mma_bf16(a0 + ntl*4, ah0, ah1, ah2, ah3, bh.x, bh.y);
            mma_bf16(a1 + ntl*4, ah0, ah1, ah2, ah3, bl.x, bl.y);
            mma_bf16(a2 + ntl*4, al0, al1, al2, al3, bh.x, bh.y);
        }
    }
#pragma unroll
    for (int i = 0; i < 8; i++) dout[i] = a0[i] + a1[i] + a2[i];
}

// GEMM, B streamed from global (L2). All 32 B-frag loads issued up front.
__device__ __forceinline__ void gemm48g(uint32_t ab_u32, uint32_t aoff,
                                        const char* gw, uint32_t boff,
                                        float* dout) {
    uint2 BH[16], BL[16];
#pragma unroll
    for (int s = 0; s < 8; s++) {
#pragma unroll
        for (int ntl = 0; ntl < 2; ntl++) {
            const char* bb = gw + boff + ntl*4096 + s*256;
            BH[s*2+ntl] = __ldg((const uint2*)bb);
            BL[s*2+ntl] = __ldg((const uint2*)(bb + 2048));
        }
    }
    float a0[8], a1[8], a2[8];
#pragma unroll
    for (int i = 0; i < 8; i++) { a0[i] = 0.f; a1[i] = 0.f; a2[i] = 0.f; }
#pragma unroll
    for (int s = 0; s < 8; s++) {
        uint32_t ah0, ah1, ah2, ah3, al0, al1, al2, al3;
        const uint32_t aa = ab_u32 + aoff + s*32;
        ldsm4(ah0, ah1, ah2, ah3, aa);
        ldsm4(al0, al1, al2, al3, aa + 256);
#pragma unroll
        for (int ntl = 0; ntl < 2; ntl++) {
            const uint2 bh = BH[s*2+ntl];
            const uint2 bl = BL[s*2+ntl];
            mma_bf16(a0 + ntl*4, ah0, ah1, ah2, ah3, bh.x, bh.y);
            mma_bf16(a1 + ntl*4, ah0, ah1, ah2, ah3, bl.x, bl.y);
            mma_bf16(a2 + ntl*4, al0, al1, al2, al3, bh.x, bh.y);
        }
    }
#pragma unroll
    for (int i = 0; i < 8; i++) dout[i] = a0[i] + a1[i] + a2[i];
}

// L1 dual GEMM: W1 (SMEM) -> zout and Whh (L2-stream) -> swout, shared A-frags.
// Whh B-loads issue first; their L2 latency hides under the W1 HMMA stream.
__device__ __forceinline__ void gemm_dual(uint32_t ab_u32, uint32_t aoff,
                                          const char* wf1, const char* gwh,
                                          uint32_t boff,
                                          float* zout, float* swout) {
    uint2 BH[16], BL[16];
#pragma unroll
    for (int s = 0; s < 8; s++) {
#pragma unroll
        for (int ntl = 0; ntl < 2; ntl++) {
            const char* bb = gwh + boff + ntl*4096 + s*256;
            BH[s*2+ntl] = __ldg((const uint2*)bb);
            BL[s*2+ntl] = __ldg((const uint2*)(bb + 2048));
        }
    }
    float z0[8], z1a[8], z2[8], s0[8], s1[8], s2[8];
#pragma unroll
    for (int i = 0; i < 8; i++) {
        z0[i] = 0.f; z1a[i] = 0.f; z2[i] = 0.f;
        s0[i] = 0.f; s1[i] = 0.f; s2[i] = 0.f;
    }
#pragma unroll
    for (int s = 0; s < 8; s++) {
        uint32_t ah0, ah1, ah2, ah3, al0, al1, al2, al3;
        const uint32_t aa = ab_u32 + aoff + s*32;
        ldsm4(ah0, ah1, ah2, ah3, aa);
        ldsm4(al0, al1, al2, al3, aa + 256);
#pragma unroll
        for (int ntl = 0; ntl < 2; ntl++) {
            const char* bb = wf1 + boff + ntl*4096 + s*256;
            const uint2 bh = *(const uint2*)bb;
            const uint2 bl = *(const uint2*)(bb + 2048);
            mma_bf16(z0 + ntl*4, ah0, ah1, ah2, ah3, bh.x, bh.y);
            mma_bf16(z1a + ntl*4, ah0, ah1, ah2, ah3, bl.x, bl.y);
            mma_bf16(z2 + ntl*4, al0, al1, al2, al3, bh.x, bh.y);
            const uint2 wh = BH[s*2+ntl];
            const uint2 wl = BL[s*2+ntl];
            mma_bf16(s0 + ntl*4, ah0, ah1, ah2, ah3, wh.x, wh.y);
            mma_bf16(s1 + ntl*4, ah0, ah1, ah2, ah3, wl.x, wl.y);
            mma_bf16(s2 + ntl*4, al0, al1, al2, al3, wh.x, wh.y);
        }
    }
#pragma unroll
    for (int i = 0; i < 8; i++) {
        zout[i]  = z0[i] + z1a[i] + z2[i];
        swout[i] = s0[i] + s1[i] + s2[i];
    }
}

// ---- prep kernels ----
__global__ void prep_mm(const float* __restrict__ A, const float* __restrict__ B,
                        int sel) {
    __shared__ float arow[H];
    const int j = blockIdx.x, k = threadIdx.x;
    arow[k] = A[j * H + k];
    __syncthreads();
    float s = 0.0f;
#pragma unroll 8
    for (int m = 0; m < H; m++) s = fmaf(arow[m], B[m * H + k], s);
    (sel ? g_Q : g_P)[j * H + k] = s;
}

__global__ void prep_frag(const float* __restrict__ W, int sel) {
    const int fi = blockIdx.x * blockDim.x + threadIdx.x;  // 0..4095
    const int ntile = fi >> 8, ks = (fi >> 5) & 7, ln = fi & 31;
    const int n = ntile * 8 + (ln >> 2);
    const int k0 = ks * 16 + 2 * (ln & 3);
    const float w00 = W[n*H + k0],     w01 = W[n*H + k0 + 1];
    const float w10 = W[n*H + k0 + 8], w11 = W[n*H + k0 + 9];
    const __nv_bfloat16 a00 = __float2bfloat16(w00), a01 = __float2bfloat16(w01);
    const __nv_bfloat16 a10 = __float2bfloat16(w10), a11 = __float2bfloat16(w11);
    uint2 hi, lo;
    hi.x = (uint32_t)__bfloat16_as_ushort(a00) | ((uint32_t)__bfloat16_as_ushort(a01) << 16);
    hi.y = (uint32_t)__bfloat16_as_ushort(a10) | ((uint32_t)__bfloat16_as_ushort(a11) << 16);
    lo.x = pkbf(w00 - __bfloat162float(a00), w01 - __bfloat162float(a01));
    lo.y = pkbf(w10 - __bfloat162float(a10), w11 - __bfloat162float(a11));
    char* base = (char*)(sel ? g_Whf : g_W2f) + ntile*4096 + ks*256 + ln*8;
    *(uint2*)base          = hi;
    *(uint2*)(base + 2048) = lo;
}

__global__ void __launch_bounds__(NTH, 1)
rnnode_mma(const float* __restrict__ x, const float* __restrict__ span,
           const float* __restrict__ W_emb, const float* __restrict__ b_emb,
           const float* __restrict__ W_ih, const float* __restrict__ b_ih,
           const float* __restrict__ W_hh, const float* __restrict__ b_hh,
           const float* __restrict__ W1, const float* __restrict__ b1,
           const float* __restrict__ W2, const float* __restrict__ b2,
           const float* __restrict__ W_out, const float* __restrict__ b_out,
           float* __restrict__ out) {
    extern __shared__ char smc[];
    const uint32_t smb = smem_u32(smc);
    const int tid = threadIdx.x;
    const int lane = tid & 31, wid = tid >> 5;
    const int bb0 = blockIdx.x * NB;
    float* xs = (float*)(smc + SM_XS);

    // ---- fill SMEM weight fragment buffers (W1, P, Q) in B-fragment order ----
#pragma unroll 1
    for (int m = 0; m < 3; m++) {
        const float* W = (m == 0) ? W1 : (m == 1) ? g_P : g_Q;
        char* wf = smc + (m == 0 ? SM_WF1 : m == 1 ? SM_WFP : SM_WFQ);
        for (int fi = tid; fi < 4096; fi += NTH) {
            const int ntile = fi >> 8, ks = (fi >> 5) & 7, ln = fi & 31;
            const int n = ntile * 8 + (ln >> 2);
            const int k0 = ks * 16 + 2 * (ln & 3);
            const float w00 = W[n*H + k0],     w01 = W[n*H + k0 + 1];
            const float w10 = W[n*H + k0 + 8], w11 = W[n*H + k0 + 9];
            uint2 hi, lo;
            pack_hl(w00, w01, hi.x, lo.x);
            pack_hl(w10, w11, hi.y, lo.y);
            const uint32_t base = ntile*4096 + ks*256 + ln*8;
            *(uint2*)(wf + base)        = hi;
            *(uint2*)(wf + base + 2048) = lo;
        }
    }

    // ---- per-thread fragment geometry ----
    const int g0 = lane >> 2, tq = lane & 3;
    const int r0 = g0, r1 = g0 + 8;
    const int cb0 = wid * 16 + 2 * tq;
    const uint32_t o00 = (uint32_t)(r0 * ROWB + cb0 * 2);
    const uint32_t o10 = (uint32_t)(r1 * ROWB + cb0 * 2);
    const uint32_t arow = (uint32_t)((((lane >> 3) & 1) * 8) + (lane & 7));
    const uint32_t aoff = arow * ROWB + (((lane >> 4) & 1) * 8) * 2;
    const uint32_t boff = (uint32_t)((wid * 2) * 4096 + lane * 8);

    // ---- per-col constants for cols {cb0, cb0+1, cb0+8, cb0+9} ----
    float cv[4], ccst[4], b1c[4], b2c[4], c1c[4], cwc[4];
#pragma unroll
    for (int q = 0; q < 4; q++) {
        const int col = cb0 + (q >> 1) * 8 + (q & 1);
        float vv = 0.0f, cc = 0.0f;
        for (int d = 0; d < D_IN; d++) {
            const float w = W_ih[col * D_IN + d];
            vv = fmaf(w, W_emb[d], vv);
            cc = fmaf(w, b_emb[d], cc);
        }
        cv[q] = vv;
        ccst[q] = cc + b_ih[col] + b_hh[col];
        b1c[q] = b1[col];
        b2c[q] = b2[col];
        float c1v = 0.0f, cwv = 0.0f;
        for (int k = 0; k < H; k++) {
            c1v = fmaf(b2[k], W1[col * H + k], c1v);
            cwv = fmaf(b2[k], W_hh[col * H + k], cwv);
        }
        c1c[q] = c1v;   // b2 @ W1^T
        cwc[q] = cwv;   // b2 @ Whh^T
    }
    if (tid < NB) xs[tid] = x[(size_t)(bb0 + tid) * T_SZ];
    __syncthreads();

    const uint32_t abu[2] = {smb + SM_AB0, smb + SM_AB1};
    char* abp[2] = {smc + SM_AB0, smc + SM_AB1};
    const char* wf1 = smc + SM_WF1;
    const char* wfp = smc + SM_WFP;
    const char* wfq = smc + SM_WFQ;
    const char* gw2 = (const char*)g_W2f;
    const char* gwh = (const char*)g_Whf;

#define QSEL(i) (((i) >> 2) * 2 + ((i) & 1))
#define RSEL(i) ((((i) >> 1) & 1))

    // htan_0 = tanh(x_0*v + c)   (s_0 = 0 since h_0 = 0)
    float htan[8], sW[8], z1[8], u1[8], u2[8], u3[8], g[8];
    {
        const float xr[2] = {xs[r0], xs[r1]};
#pragma unroll
        for (int i = 0; i < 8; i++) {
            const int q = QSEL(i);
            htan[i] = tanh_hw(fmaf(xr[RSEL(i)], cv[q], ccst[q]));
        }
    }
    int p = 0;
    float dtL = 1.0f;

#pragma unroll 1
    for (int t = 0; t < NSTEPS; t++) {
        const float dt   = __ldg(span + t + 1) - __ldg(span + t);
        const float dt3  = dt * (1.0f / 3.0f);
        const float dt23 = 2.0f * dt3;
        const float dt8  = dt * 0.125f;
        dtL = dt;

        // L1: stage htan; dual GEMM: W1 (SMEM) -> z1, Whh (L2) -> sW
        stage8(abp[p], htan, o00, o10);
        if (tid < NB) xs[tid] = x[(size_t)(bb0 + tid) * T_SZ + (t + 1)];
        __syncthreads();
        gemm_dual(abu[p], aoff, wf1, gwh, boff, g, sW);
        p ^= 1;
#pragma unroll
        for (int i = 0; i < 8; i++) {
            z1[i] = g[i] + b1c[QSEL(i)];
            u1[i] = silu_f(z1[i]);
        }
        // L2: u2 = silu(z1 + dt/3*(u1@P^T + c1))
        stage8(abp[p], u1, o00, o10);
        __syncthreads();
        gemm48s(abu[p], aoff, wfp, boff, g);
        p ^= 1;
#pragma unroll
        for (int i = 0; i < 8; i++) {
            u2[i] = silu_f(fmaf(dt3, g[i] + c1c[QSEL(i)], z1[i]));
            g[i] = fmaf(-(1.0f / 3.0f), u1[i], u2[i]);
        }
        // L3: u3 = silu(z1 + dt*((u2-u1/3)@P^T) + 2dt/3*c1)
        stage8(abp[p], g, o00, o10);
        __syncthreads();
        gemm48s(abu[p], aoff, wfp, boff, g);
        p ^= 1;
#pragma unroll
        for (int i = 0; i < 8; i++) {
            u3[i] = silu_f(fmaf(dt, g[i], fmaf(dt23, c1c[QSEL(i)], z1[i])));
            g[i] = u1[i] - u2[i] + u3[i];
        }
        // L4: u4 = silu(z1 + dt*((u1-u2+u3)@P^T + c1)); g4 = u1+3(u2+u3)+u4
        stage8(abp[p], g, o00, o10);
        __syncthreads();
        gemm48s(abu[p], aoff, wfp, boff, g);
        p ^= 1;
#pragma unroll
        for (int i = 0; i < 8; i++) {
            const float u4 = silu_f(fmaf(dt, g[i] + c1c[QSEL(i)], z1[i]));
            g[i] = fmaf(3.0f, u2[i] + u3[i], u1[i] + u4);
        }
        // L5 (skip on last step): s+ = sW + dt/8*(g4@Q^T) + dt*cw ;
        //                         htan+ = tanh(x+*v + c + s+)
        stage8(abp[p], g, o00, o10);
        __syncthreads();
        if (t + 1 < NSTEPS) {
            gemm48s(abu[p], aoff, wfq, boff, g);
            p ^= 1;
            const float xr[2] = {xs[r0], xs[r1]};
#pragma unroll
            for (int i = 0; i < 8; i++) {
                const int q = QSEL(i);
                const float s = fmaf(dt8, g[i], fmaf(dt, cwc[q], sW[i]));
                htan[i] = tanh_hw(fmaf(xr[RSEL(i)], cv[q], ccst[q]) + s);
            }
        }
    }

    // ---- final h = htan + dt/8*(g4@W2^T) + dt*b2 (g4 staged in buf p) ----
    {
        gemm48g(abu[p], aoff, gw2, boff, g);
        const float dt8L = dtL * 0.125f;
#pragma unroll
        for (int i = 0; i < 8; i++)
            htan[i] = fmaf(dt8L, g[i], fmaf(dtL, b2c[QSEL(i)], htan[i]));
    }

    // ---- epilogue: out = h @ W_out^T + b_out ----
    __syncthreads();
    float* hb = (float*)smc;  // reuse WF1 region: [16][128] fp32
#pragma unroll
    for (int ntl = 0; ntl < 2; ntl++) {
        const int c = cb0 + ntl * 8;
        hb[r0 * H + c]     = htan[ntl*4+0];
        hb[r0 * H + c + 1] = htan[ntl*4+1];
        hb[r1 * H + c]     = htan[ntl*4+2];
        hb[r1 * H + c + 1] = htan[ntl*4+3];
    }
    __syncthreads();
    {
        const int j = tid & 63, q = tid >> 6;
        float o[4];
        const float bo = __ldg(b_out + j);
#pragma unroll
        for (int n = 0; n < 4; n++) o[n] = bo;
        const float* Wo = W_out + j * H;
#pragma unroll 4
        for (int k = 0; k < H; k++) {
            const float wv = __ldg(Wo + k);
            const float* ar = hb + (q * 4) * H + k;
#pragma unroll
            for (int n = 0; n < 4; n++) o[n] = fmaf(ar[n * H], wv, o[n]);
        }
#pragma unroll
        for (int n = 0; n < 4; n++)
            out[(size_t)(bb0 + q * 4 + n) * D_OUT + j] = o[n];
    }
}

extern "C" void kernel_launch(void* const* d_in, const int* in_sizes, int n_in,
                              void* d_out, int out_size) {
    const float* x     = (const float*)d_in[0];
    const float* span  = (const float*)d_in[1];
    const float* W_emb = (const float*)d_in[2];
    const float* b_emb = (const float*)d_in[3];
    const float* W_ih  = (const float*)d_in[4];
    const float* b_ih  = (const float*)d_in[5];
    const float* W_hh  = (const float*)d_in[6];
    const float* b_hh  = (const float*)d_in[7];
    const float* W1    = (const float*)d_in[8];
    const float* b1    = (const float*)d_in[9];
    const float* W2    = (const float*)d_in[10];
    const float* b2    = (const float*)d_in[11];
    const float* W_out = (const float*)d_in[12];
    const float* b_out = (const float*)d_in[13];
    float* out = (float*)d_out;

    prep_mm<<<H, H>>>(W1, W2, 0);     // P = W1 @ W2
    prep_mm<<<H, H>>>(W_hh, W2, 1);   // Q = Whh @ W2
    prep_frag<<<16, 256>>>(W2, 0);
    prep_frag<<<16, 256>>>(W_hh, 1);
    cudaFuncSetAttribute(rnnode_mma, cudaFuncAttributeMaxDynamicSharedMemorySize,
                         SMEM_BYTES);
    rnnode_mma<<<B_SZ / NB, NTH, SMEM_BYTES>>>(
        x, span, W_emb, b_emb, W_ih, b_ih, W_hh, b_hh,
        W1, b1, W2, b2, W_out, b_out, out);
}

// round 14
// speedup vs baseline: 4.3969x; 1.1120x over previous
#include <cuda_runtime.h>
#include <cuda_bf16.h>
#include <stdint.h>
#include <math.h>

#define B_SZ 2048
#define T_SZ 512
#define D_IN 64
#define H    128
#define D_OUT 64
#define NB   16
#define NTH  256
#define NSTEPS (T_SZ-1)
#define ROWB 528   // activation buffer row stride in bytes (264 bf16)

// SMEM byte offsets
#define SM_WF1 0        // W1 fragments (64KB, uint4-interleaved hi|lo)
#define SM_WFP 65536    // P fragments
#define SM_WFQ 131072   // Q fragments
#define SM_AB0 196608   // activation ping  [16][264] bf16
#define SM_AB1 205056   // activation pong
#define SM_XS  213504   // 16 floats
#define SMEM_BYTES 213568

__device__ float g_P[H * H];               // P = W1 @ W2   (row-major [j][k])
__device__ float g_Q[H * H];               // Q = Whh @ W2  (row-major [j][k])
__device__ unsigned long long g_W2f[8192]; // W2 fragments (64KB, uint4 layout)
__device__ unsigned long long g_Whf[8192]; // Whh fragments (64KB, uint4 layout)

__device__ __forceinline__ uint32_t smem_u32(const void* p) {
    uint32_t a;
    asm("{ .reg .u64 t; cvta.to.shared.u64 t, %1; cvt.u32.u64 %0, t; }" : "=r"(a) : "l"(p));
    return a;
}
__device__ __forceinline__ void ldsm4(uint32_t& r0, uint32_t& r1, uint32_t& r2,
                                      uint32_t& r3, uint32_t addr) {
    asm volatile("ldmatrix.sync.aligned.m8n8.x4.shared.b16 {%0,%1,%2,%3}, [%4];"
                 : "=r"(r0), "=r"(r1), "=r"(r2), "=r"(r3) : "r"(addr));
}
__device__ __forceinline__ void mma_bf16(float* d, uint32_t a0, uint32_t a1,
                                         uint32_t a2, uint32_t a3,
                                         uint32_t b0, uint32_t b1) {
    asm volatile("mma.sync.aligned.m16n8k16.row.col.f32.bf16.bf16.f32 "
                 "{%0,%1,%2,%3}, {%4,%5,%6,%7}, {%8,%9}, {%0,%1,%2,%3};"
                 : "+f"(d[0]), "+f"(d[1]), "+f"(d[2]), "+f"(d[3])
                 : "r"(a0), "r"(a1), "r"(a2), "r"(a3), "r"(b0), "r"(b1));
}
__device__ __forceinline__ float tanh_hw(float v) {
    float t;
    asm("tanh.approx.f32 %0, %1;" : "=f"(t) : "f"(v));
    return t;
}
__device__ __forceinline__ float silu_f(float v) {
    const float hv = 0.5f * v;
    return fmaf(hv, tanh_hw(hv), hv);
}

// Pack (d0,d1) -> bf16x2 hi word + bf16x2 lo-residual word.
__device__ __forceinline__ void pack_hl(float d0, float d1, uint32_t& hp, uint32_t& lp) {
    asm("cvt.rn.bf16x2.f32 %0, %1, %2;" : "=r"(hp) : "f"(d1), "f"(d0));
    const float f0 = __uint_as_float(hp << 16);
    const float f1 = __uint_as_float(hp & 0xFFFF0000u);
    asm("cvt.rn.bf16x2.f32 %0, %1, %2;" : "=r"(lp) : "f"(d1 - f1), "f"(d0 - f0));
}

// Stage 8 fragment values into activation buffer as bf16 hi (+0) / lo (+256B).
__device__ __forceinline__ void stage8(char* ab, const float* v,
                                       uint32_t o00, uint32_t o10) {
#pragma unroll
    for (int ntl = 0; ntl < 2; ntl++) {
        const uint32_t oa = o00 + ntl*16, ob = o10 + ntl*16;
        uint32_t hp, lp;
        pack_hl(v[ntl*4+0], v[ntl*4+1], hp, lp);
        *(uint32_t*)(ab + oa) = hp;
        *(uint32_t*)(ab + oa + 256) = lp;
        pack_hl(v[ntl*4+2], v[ntl*4+3], hp, lp);
        *(uint32_t*)(ab + ob) = hp;
        *(uint32_t*)(ab + ob + 256) = lp;
    }
}

// Fragment uint4 layout: addr = ntile*4096 + s*512 + lane*16 ;
// v = {hiB0, hiB1, loB0, loB1}

// GEMM, B from SMEM (uint4 loads), 3 accumulator groups.
__device__ __forceinline__ void gemm48s(uint32_t ab_u32, uint32_t aoff,
                                        const char* wf, uint32_t boff,
                                        float* dout) {
    float a0[8], a1[8], a2[8];
#pragma unroll
    for (int i = 0; i < 8; i++) { a0[i] = 0.f; a1[i] = 0.f; a2[i] = 0.f; }
#pragma unroll
    for (int s = 0; s < 8; s++) {
        uint32_t ah0, ah1, ah2, ah3, al0, al1, al2, al3;
        const uint32_t aa = ab_u32 + aoff + s*32;
        ldsm4(ah0, ah1, ah2, ah3, aa);
        ldsm4(al0, al1, al2, al3, aa + 256);
#pragma unroll
        for (int ntl = 0; ntl < 2; ntl++) {
            const uint4 b = *(const uint4*)(wf + boff + ntl*4096 + s*512);
            mma_bf16(a0 + ntl*4, ah0, ah1, ah2, ah3, b.x, b.y);
            mma_bf16(a1 + ntl*4, ah0, ah1, ah2, ah3, b.z, b.w);
            mma_bf16(a2 + ntl*4, al0, al1, al2, al3, b.x, b.y);
        }
    }
#pragma unroll
    for (int i = 0; i < 8; i++) dout[i] = a0[i] + a1[i] + a2[i];
}

// GEMM, B from persistent registers (P matrix).
__device__ __forceinline__ void gemm48r(uint32_t ab_u32, uint32_t aoff,
                                        const uint4* PB, float* dout) {
    float a0[8], a1[8], a2[8];
#pragma unroll
    for (int i = 0; i < 8; i++) { a0[i] = 0.f; a1[i] = 0.f; a2[i] = 0.f; }
#pragma unroll
    for (int s = 0; s < 8; s++) {
        uint32_t ah0, ah1, ah2, ah3, al0, al1, al2, al3;
        const uint32_t aa = ab_u32 + aoff + s*32;
        ldsm4(ah0, ah1, ah2, ah3, aa);
        ldsm4(al0, al1, al2, al3, aa + 256);
#pragma unroll
        for (int ntl = 0; ntl < 2; ntl++) {
            const uint4 b = PB[s*2 + ntl];
            mma_bf16(a0 + ntl*4, ah0, ah1, ah2, ah3, b.x, b.y);
            mma_bf16(a1 + ntl*4, ah0, ah1, ah2, ah3, b.z, b.w);
            mma_bf16(a2 + ntl*4, al0, al1, al2, al3, b.x, b.y);
        }
    }
#pragma unroll
    for (int i = 0; i < 8; i++) dout[i] = a0[i] + a1[i] + a2[i];
}

// GEMM, B streamed from global (L2), uint4 loads.
__device__ __forceinline__ void gemm48g(uint32_t ab_u32, uint32_t aoff,
                                        const char* gw, uint32_t boff,
                                        float* dout) {
    uint4 B[16];
#pragma unroll
    for (int s = 0; s < 8; s++)
#pragma unroll
        for (int ntl = 0; ntl < 2; ntl++)
            B[s*2+ntl] = __ldg((const uint4*)(gw + boff + ntl*4096 + s*512));
    float a0[8], a1[8], a2[8];
#pragma unroll
    for (int i = 0; i < 8; i++) { a0[i] = 0.f; a1[i] = 0.f; a2[i] = 0.f; }
#pragma unroll
    for (int s = 0; s < 8; s++) {
        uint32_t ah0, ah1, ah2, ah3, al0, al1, al2, al3;
        const uint32_t aa = ab_u32 + aoff + s*32;
        ldsm4(ah0, ah1, ah2, ah3, aa);
        ldsm4(al0, al1, al2, al3, aa + 256);
#pragma unroll
        for (int ntl = 0; ntl < 2; ntl++) {
            const uint4 b = B[s*2+ntl];
            mma_bf16(a0 + ntl*4, ah0, ah1, ah2, ah3, b.x, b.y);
            mma_bf16(a1 + ntl*4, ah0, ah1, ah2, ah3, b.z, b.w);
            mma_bf16(a2 + ntl*4, al0, al1, al2, al3, b.x, b.y);
        }
    }
#pragma unroll
    for (int i = 0; i < 8; i++) dout[i] = a0[i] + a1[i] + a2[i];
}

// L1 dual GEMM: W1 (SMEM) -> zout and Whh (L2, in-loop ldg) -> swout.
__device__ __forceinline__ void gemm_dual(uint32_t ab_u32, uint32_t aoff,
                                          const char* wf1, const char* gwh,
                                          uint32_t boff,
                                          float* zout, float* swout) {
    float z0[8], z1a[8], z2[8], s0[8], s1[8], s2[8];
#pragma unroll
    for (int i = 0; i < 8; i++) {
        z0[i] = 0.f; z1a[i] = 0.f; z2[i] = 0.f;
        s0[i] = 0.f; s1[i] = 0.f; s2[i] = 0.f;
    }
#pragma unroll
    for (int s = 0; s < 8; s++) {
        uint32_t ah0, ah1, ah2, ah3, al0, al1, al2, al3;
        const uint32_t aa = ab_u32 + aoff + s*32;
        ldsm4(ah0, ah1, ah2, ah3, aa);
        ldsm4(al0, al1, al2, al3, aa + 256);
#pragma unroll
        for (int ntl = 0; ntl < 2; ntl++) {
            const uint4 b = *(const uint4*)(wf1 + boff + ntl*4096 + s*512);
            const uint4 w = __ldg((const uint4*)(gwh + boff + ntl*4096 + s*512));
            mma_bf16(z0 + ntl*4, ah0, ah1, ah2, ah3, b.x, b.y);
            mma_bf16(z1a + ntl*4, ah0, ah1, ah2, ah3, b.z, b.w);
            mma_bf16(z2 + ntl*4, al0, al1, al2, al3, b.x, b.y);
            mma_bf16(s0 + ntl*4, ah0, ah1, ah2, ah3, w.x, w.y);
            mma_bf16(s1 + ntl*4, ah0, ah1, ah2, ah3, w.z, w.w);
            mma_bf16(s2 + ntl*4, al0, al1, al2, al3, w.x, w.y);
        }
    }
#pragma unroll
    for (int i = 0; i < 8; i++) {
        zout[i]  = z0[i] + z1a[i] + z2[i];
        swout[i] = s0[i] + s1[i] + s2[i];
    }
}

// ---- prep kernels ----
__global__ void prep_mm(const float* __restrict__ A, const float* __restrict__ B,
                        int sel) {
    __shared__ float arow[H];
    const int j = blockIdx.x, k = threadIdx.x;
    arow[k] = A[j * H + k];
    __syncthreads();
    float s = 0.0f;
#pragma unroll 8
    for (int m = 0; m < H; m++) s = fmaf(arow[m], B[m * H + k], s);
    (sel ? g_Q : g_P)[j * H + k] = s;
}

__global__ void prep_frag(const float* __restrict__ W, int sel) {
    const int fi = blockIdx.x * blockDim.x + threadIdx.x;  // 0..4095
    const int ntile = fi >> 8, s = (fi >> 5) & 7, ln = fi & 31;
    const int n = ntile * 8 + (ln >> 2);
    const int k0 = s * 16 + 2 * (ln & 3);
    const float w00 = W[n*H + k0],     w01 = W[n*H + k0 + 1];
    const float w10 = W[n*H + k0 + 8], w11 = W[n*H + k0 + 9];
    uint4 v;
    pack_hl(w00, w01, v.x, v.z);
    pack_hl(w10, w11, v.y, v.w);
    char* base = (char*)(sel ? g_Whf : g_W2f) + ntile*4096 + s*512 + ln*16;
    *(uint4*)base = v;
}

__global__ void __launch_bounds__(NTH, 1)
rnnode_mma(const float* __restrict__ x, const float* __restrict__ span,
           const float* __restrict__ W_emb, const float* __restrict__ b_emb,
           const float* __restrict__ W_ih, const float* __restrict__ b_ih,
           const float* __restrict__ W_hh, const float* __restrict__ b_hh,
           const float* __restrict__ W1, const float* __restrict__ b1,
           const float* __restrict__ W2, const float* __restrict__ b2,
           const float* __restrict__ W_out, const float* __restrict__ b_out,
           float* __restrict__ out) {
    extern __shared__ char smc[];
    const uint32_t smb = smem_u32(smc);
    const int tid = threadIdx.x;
    const int lane = tid & 31, wid = tid >> 5;
    const int bb0 = blockIdx.x * NB;
    float* xs = (float*)(smc + SM_XS);

    // ---- fill SMEM weight fragment buffers (W1, P, Q), uint4 layout ----
#pragma unroll 1
    for (int m = 0; m < 3; m++) {
        const float* W = (m == 0) ? W1 : (m == 1) ? g_P : g_Q;
        char* wf = smc + (m == 0 ? SM_WF1 : m == 1 ? SM_WFP : SM_WFQ);
        for (int fi = tid; fi < 4096; fi += NTH) {
            const int ntile = fi >> 8, s = (fi >> 5) & 7, ln = fi & 31;
            const int n = ntile * 8 + (ln >> 2);
            const int k0 = s * 16 + 2 * (ln & 3);
            const float w00 = W[n*H + k0],     w01 = W[n*H + k0 + 1];
            const float w10 = W[n*H + k0 + 8], w11 = W[n*H + k0 + 9];
            uint4 v;
            pack_hl(w00, w01, v.x, v.z);
            pack_hl(w10, w11, v.y, v.w);
            *(uint4*)(wf + ntile*4096 + s*512 + ln*16) = v;
        }
    }

    // ---- per-thread fragment geometry ----
    const int g0 = lane >> 2, tq = lane & 3;
    const int r0 = g0, r1 = g0 + 8;
    const int cb0 = wid * 16 + 2 * tq;
    const uint32_t o00 = (uint32_t)(r0 * ROWB + cb0 * 2);
    const uint32_t o10 = (uint32_t)(r1 * ROWB + cb0 * 2);
    const uint32_t arow = (uint32_t)((((lane >> 3) & 1) * 8) + (lane & 7));
    const uint32_t aoff = arow * ROWB + (((lane >> 4) & 1) * 8) * 2;
    const uint32_t boff = (uint32_t)((wid * 2) * 4096 + lane * 16);

    // ---- per-col constants for cols {cb0, cb0+1, cb0+8, cb0+9} ----
    float cv[4], ccst[4], b1c[4], b2c[4], c1c[4], cwc[4];
#pragma unroll
    for (int q = 0; q < 4; q++) {
        const int col = cb0 + (q >> 1) * 8 + (q & 1);
        float vv = 0.0f, cc = 0.0f;
        for (int d = 0; d < D_IN; d++) {
            const float w = W_ih[col * D_IN + d];
            vv = fmaf(w, W_emb[d], vv);
            cc = fmaf(w, b_emb[d], cc);
        }
        cv[q] = vv;
        ccst[q] = cc + b_ih[col] + b_hh[col];
        b1c[q] = b1[col];
        b2c[q] = b2[col];
        float c1v = 0.0f, cwv = 0.0f;
        for (int k = 0; k < H; k++) {
            c1v = fmaf(b2[k], W1[col * H + k], c1v);
            cwv = fmaf(b2[k], W_hh[col * H + k], cwv);
        }
        c1c[q] = c1v;   // b2 @ W1^T
        cwc[q] = cwv;   // b2 @ Whh^T
    }
    if (tid < NB) xs[tid] = x[(size_t)(bb0 + tid) * T_SZ];
    __syncthreads();

    const uint32_t abu[2] = {smb + SM_AB0, smb + SM_AB1};
    char* abp[2] = {smc + SM_AB0, smc + SM_AB1};
    const char* wf1 = smc + SM_WF1;
    const char* wfq = smc + SM_WFQ;
    const char* gw2 = (const char*)g_W2f;
    const char* gwh = (const char*)g_Whf;

    // ---- persistent P B-fragments (16 uint4 = 64 regs) ----
    uint4 PB[16];
    {
        const char* wfp = smc + SM_WFP;
#pragma unroll
        for (int idx = 0; idx < 16; idx++) {
            const int s = idx >> 1, ntl = idx & 1;
            PB[idx] = *(const uint4*)(wfp + boff + ntl*4096 + s*512);
        }
    }

#define QSEL(i) (((i) >> 2) * 2 + ((i) & 1))
#define RSEL(i) ((((i) >> 1) & 1))

    // htan_0 = tanh(x_0*v + c)   (s_0 = 0 since h_0 = 0)
    float htan[8], sW[8], z1[8], u1[8], u2[8], u3[8], g[8];
    {
        const float xr[2] = {xs[r0], xs[r1]};
#pragma unroll
        for (int i = 0; i < 8; i++) {
            const int q = QSEL(i);
            htan[i] = tanh_hw(fmaf(xr[RSEL(i)], cv[q], ccst[q]));
        }
    }
    int p = 0;
    float dtL = 1.0f;

#pragma unroll 1
    for (int t = 0; t < NSTEPS; t++) {
        const float dt   = __ldg(span + t + 1) - __ldg(span + t);
        const float dt3  = dt * (1.0f / 3.0f);
        const float dt23 = 2.0f * dt3;
        const float dt8  = dt * 0.125f;
        dtL = dt;

        // L1: stage htan; dual GEMM: W1 (SMEM) -> z1, Whh (L2) -> sW
        stage8(abp[p], htan, o00, o10);
        if (tid < NB) xs[tid] = x[(size_t)(bb0 + tid) * T_SZ + (t + 1)];
        __syncthreads();
        gemm_dual(abu[p], aoff, wf1, gwh, boff, g, sW);
        p ^= 1;
#pragma unroll
        for (int i = 0; i < 8; i++) {
            z1[i] = g[i] + b1c[QSEL(i)];
            u1[i] = silu_f(z1[i]);
        }
        // L2: u2 = silu(z1 + dt/3*(u1@P^T + c1))
        stage8(abp[p], u1, o00, o10);
        __syncthreads();
        gemm48r(abu[p], aoff, PB, g);
        p ^= 1;
#pragma unroll
        for (int i = 0; i < 8; i++) {
            u2[i] = silu_f(fmaf(dt3, g[i] + c1c[QSEL(i)], z1[i]));
            g[i] = fmaf(-(1.0f / 3.0f), u1[i], u2[i]);
        }
        // L3: u3 = silu(z1 + dt*((u2-u1/3)@P^T) + 2dt/3*c1)
        stage8(abp[p], g, o00, o10);
        __syncthreads();
        gemm48r(abu[p], aoff, PB, g);
        p ^= 1;
#pragma unroll
        for (int i = 0; i < 8; i++) {
            u3[i] = silu_f(fmaf(dt, g[i], fmaf(dt23, c1c[QSEL(i)], z1[i])));
            g[i] = u1[i] - u2[i] + u3[i];
        }
        // L4: u4 = silu(z1 + dt*((u1-u2+u3)@P^T + c1)); g4 = u1+3(u2+u3)+u4
        stage8(abp[p], g, o00, o10);
        __syncthreads();
        gemm48r(abu[p], aoff, PB, g);
        p ^= 1;
#pragma unroll
        for (int i = 0; i < 8; i++) {
            const float u4 = silu_f(fmaf(dt, g[i] + c1c[QSEL(i)], z1[i]));
            g[i] = fmaf(3.0f, u2[i] + u3[i], u1[i] + u4);
        }
        // L5 (skip on last step): s+ = sW + dt/8*(g4@Q^T) + dt*cw ;
        //                         htan+ = tanh(x+*v + c + s+)
        stage8(abp[p], g, o00, o10);
        __syncthreads();
        if (t + 1 < NSTEPS) {
            gemm48s(abu[p], aoff, wfq, boff, g);
            p ^= 1;
            const float xr[2] = {xs[r0], xs[r1]};
#pragma unroll
            for (int i = 0; i < 8; i++) {
                const int q = QSEL(i);
                const float s = fmaf(dt8, g[i], fmaf(dt, cwc[q], sW[i]));
                htan[i] = tanh_hw(fmaf(xr[RSEL(i)], cv[q], ccst[q]) + s);
            }
        }
    }

    // ---- final h = htan + dt/8*(g4@W2^T) + dt*b2 (g4 staged in buf p) ----
    {
        gemm48g(abu[p], aoff, gw2, boff, g);
        const float dt8L = dtL * 0.125f;
#pragma unroll
        for (int i = 0; i < 8; i++)
            htan[i] = fmaf(dt8L, g[i], fmaf(dtL, b2c[QSEL(i)], htan[i]));
    }

    // ---- epilogue: out = h @ W_out^T + b_out ----
    __syncthreads();
    float* hb = (float*)smc;  // reuse WF1 region: [16][128] fp32
#pragma unroll
    for (int ntl = 0; ntl < 2; ntl++) {
        const int c = cb0 + ntl * 8;
        hb[r0 * H + c]     = htan[ntl*4+0];
        hb[r0 * H + c + 1] = htan[ntl*4+1];
        hb[r1 * H + c]     = htan[ntl*4+2];
        hb[r1 * H + c + 1] = htan[ntl*4+3];
    }
    __syncthreads();
    {
        const int j = tid & 63, q = tid >> 6;
        float o[4];
        const float bo = __ldg(b_out + j);
#pragma unroll
        for (int n = 0; n < 4; n++) o[n] = bo;
        const float* Wo = W_out + j * H;
#pragma unroll 4
        for (int k = 0; k < H; k++) {
            const float wv = __ldg(Wo + k);
            const float* ar = hb + (q * 4) * H + k;
#pragma unroll
            for (int n = 0; n < 4; n++) o[n] = fmaf(ar[n * H], wv, o[n]);
        }
#pragma unroll
        for (int n = 0; n < 4; n++)
            out[(size_t)(bb0 + q * 4 + n) * D_OUT + j] = o[n];
    }
}

extern "C" void kernel_launch(void* const* d_in, const int* in_sizes, int n_in,
                              void* d_out, int out_size) {
    const float* x     = (const float*)d_in[0];
    const float* span  = (const float*)d_in[1];
    const float* W_emb = (const float*)d_in[2];
    const float* b_emb = (const float*)d_in[3];
    const float* W_ih  = (const float*)d_in[4];
    const float* b_ih  = (const float*)d_in[5];
    const float* W_hh  = (const float*)d_in[6];
    const float* b_hh  = (const float*)d_in[7];
    const float* W1    = (const float*)d_in[8];
    const float* b1    = (const float*)d_in[9];
    const float* W2    = (const float*)d_in[10];
    const float* b2    = (const float*)d_in[11];
    const float* W_out = (const float*)d_in[12];
    const float* b_out = (const float*)d_in[13];
    float* out = (float*)d_out;

    prep_mm<<<H, H>>>(W1, W2, 0);     // P = W1 @ W2
    prep_mm<<<H, H>>>(W_hh, W2, 1);   // Q = Whh @ W2
    prep_frag<<<16, 256>>>(W2, 0);
    prep_frag<<<16, 256>>>(W_hh, 1);
    cudaFuncSetAttribute(rnnode_mma, cudaFuncAttributeMaxDynamicSharedMemorySize,
                         SMEM_BYTES);
    rnnode_mma<<<B_SZ / NB, NTH, SMEM_BYTES>>>(
        x, span, W_emb, b_emb, W_ih, b_ih, W_hh, b_hh,
        W1, b1, W2, b2, W_out, b_out, out);
}

// round 15
// speedup vs baseline: 5.8157x; 1.3227x over previous
#include <cuda_runtime.h>
#include <cuda_fp16.h>
#include <stdint.h>
#include <math.h>

#define B_SZ 2048
#define T_SZ 512
#define D_IN 64
#define H    128
#define D_OUT 64
#define NB   16
#define NTH  256
#define NSTEPS (T_SZ-1)
#define ROWB 272   // activation buffer row stride in bytes (128 fp16 + 16B pad)

// SMEM byte offsets
#define SM_WF1 0        // W1 fragments (64KB, uint4 {b0h,b1h,b0l,b1l} fp16)
#define SM_WFP 65536    // P fragments
#define SM_WFQ 131072   // Q fragments
#define SM_AB0 196608   // activation ping  [16][ROWB] fp16 (4352B)
#define SM_AB1 200960   // activation pong
#define SM_XS  205312   // 16 floats
#define SMEM_BYTES 205376

__device__ float g_P[H * H];               // P = W1 @ W2   (row-major [j][k])
__device__ float g_Q[H * H];               // Q = Whh @ W2  (row-major [j][k])
__device__ unsigned long long g_W2f[8192]; // W2 fragments (64KB, uint4 layout)
__device__ unsigned long long g_Whf[8192]; // Whh fragments (64KB, uint4 layout)

__device__ __forceinline__ uint32_t smem_u32(const void* p) {
    uint32_t a;
    asm("{ .reg .u64 t; cvta.to.shared.u64 t, %1; cvt.u32.u64 %0, t; }" : "=r"(a) : "l"(p));
    return a;
}
__device__ __forceinline__ uint32_t pk2h(float a, float b) {
    __half2 h = __floats2half2_rn(a, b);
    return *(uint32_t*)&h;
}
// hi fp16x2 + lo residual fp16x2
__device__ __forceinline__ void pack_hl(float d0, float d1, uint32_t& hp, uint32_t& lp) {
    __half2 h = __floats2half2_rn(d0, d1);
    hp = *(uint32_t*)&h;
    lp = pk2h(d0 - __low2float(h), d1 - __high2float(h));
}
__device__ __forceinline__ void ldsm4(uint32_t& r0, uint32_t& r1, uint32_t& r2,
                                      uint32_t& r3, uint32_t addr) {
    asm volatile("ldmatrix.sync.aligned.m8n8.x4.shared.b16 {%0,%1,%2,%3}, [%4];"
                 : "=r"(r0), "=r"(r1), "=r"(r2), "=r"(r3) : "r"(addr));
}
__device__ __forceinline__ void mma_f16(float* d, uint32_t a0, uint32_t a1,
                                        uint32_t a2, uint32_t a3,
                                        uint32_t b0, uint32_t b1) {
    asm volatile("mma.sync.aligned.m16n8k16.row.col.f32.f16.f16.f32 "
                 "{%0,%1,%2,%3}, {%4,%5,%6,%7}, {%8,%9}, {%0,%1,%2,%3};"
                 : "+f"(d[0]), "+f"(d[1]), "+f"(d[2]), "+f"(d[3])
                 : "r"(a0), "r"(a1), "r"(a2), "r"(a3), "r"(b0), "r"(b1));
}
__device__ __forceinline__ float tanh_hw(float v) {
    float t;
    asm("tanh.approx.f32 %0, %1;" : "=f"(t) : "f"(v));
    return t;
}
__device__ __forceinline__ float silu_f(float v) {
    const float hv = 0.5f * v;
    return fmaf(hv, tanh_hw(hv), hv);
}

// Stage 8 fragment values as single fp16 (4 STS.32 per thread).
__device__ __forceinline__ void stage8(char* ab, const float* v,
                                       uint32_t o00, uint32_t o10) {
#pragma unroll
    for (int ntl = 0; ntl < 2; ntl++) {
        *(uint32_t*)(ab + o00 + ntl*16) = pk2h(v[ntl*4+0], v[ntl*4+1]);
        *(uint32_t*)(ab + o10 + ntl*16) = pk2h(v[ntl*4+2], v[ntl*4+3]);
    }
}

// Weight fragment uint4 layout: addr = ntile*4096 + s*512 + lane*16 ;
// v = {b0_hi, b1_hi, b0_lo, b1_lo} (fp16x2 words)

// GEMM, weights from SMEM: 2 terms (Ah*Wh + Ah*Wl), 4 chains of 8.
__device__ __forceinline__ void gemm32s(uint32_t ab_u32, uint32_t aoff,
                                        const char* wf, uint32_t boff,
                                        float* dout) {
    float a0[8], a1[8];
#pragma unroll
    for (int i = 0; i < 8; i++) { a0[i] = 0.f; a1[i] = 0.f; }
#pragma unroll
    for (int s = 0; s < 8; s++) {
        uint32_t ah0, ah1, ah2, ah3;
        ldsm4(ah0, ah1, ah2, ah3, ab_u32 + aoff + s*32);
#pragma unroll
        for (int ntl = 0; ntl < 2; ntl++) {
            const uint4 b = *(const uint4*)(wf + boff + ntl*4096 + s*512);
            mma_f16(a0 + ntl*4, ah0, ah1, ah2, ah3, b.x, b.y);
            mma_f16(a1 + ntl*4, ah0, ah1, ah2, ah3, b.z, b.w);
        }
    }
#pragma unroll
    for (int i = 0; i < 8; i++) dout[i] = a0[i] + a1[i];
}

// GEMM, weights from persistent registers (P matrix).
__device__ __forceinline__ void gemm32r(uint32_t ab_u32, uint32_t aoff,
                                        const uint4* PB, float* dout) {
    float a0[8], a1[8];
#pragma unroll
    for (int i = 0; i < 8; i++) { a0[i] = 0.f; a1[i] = 0.f; }
#pragma unroll
    for (int s = 0; s < 8; s++) {
        uint32_t ah0, ah1, ah2, ah3;
        ldsm4(ah0, ah1, ah2, ah3, ab_u32 + aoff + s*32);
#pragma unroll
        for (int ntl = 0; ntl < 2; ntl++) {
            const uint4 b = PB[s*2 + ntl];
            mma_f16(a0 + ntl*4, ah0, ah1, ah2, ah3, b.x, b.y);
            mma_f16(a1 + ntl*4, ah0, ah1, ah2, ah3, b.z, b.w);
        }
    }
#pragma unroll
    for (int i = 0; i < 8; i++) dout[i] = a0[i] + a1[i];
}

// GEMM, weights streamed from global (L2), uint4 loads.
__device__ __forceinline__ void gemm32g(uint32_t ab_u32, uint32_t aoff,
                                        const char* gw, uint32_t boff,
                                        float* dout) {
    uint4 B[16];
#pragma unroll
    for (int s = 0; s < 8; s++)
#pragma unroll
        for (int ntl = 0; ntl < 2; ntl++)
            B[s*2+ntl] = __ldg((const uint4*)(gw + boff + ntl*4096 + s*512));
    float a0[8], a1[8];
#pragma unroll
    for (int i = 0; i < 8; i++) { a0[i] = 0.f; a1[i] = 0.f; }
#pragma unroll
    for (int s = 0; s < 8; s++) {
        uint32_t ah0, ah1, ah2, ah3;
        ldsm4(ah0, ah1, ah2, ah3, ab_u32 + aoff + s*32);
#pragma unroll
        for (int ntl = 0; ntl < 2; ntl++) {
            const uint4 b = B[s*2+ntl];
            mma_f16(a0 + ntl*4, ah0, ah1, ah2, ah3, b.x, b.y);
            mma_f16(a1 + ntl*4, ah0, ah1, ah2, ah3, b.z, b.w);
        }
    }
#pragma unroll
    for (int i = 0; i < 8; i++) dout[i] = a0[i] + a1[i];
}

// L1 dual GEMM: W1 (SMEM) -> zout and Whh (L2, in-loop ldg) -> swout.
__device__ __forceinline__ void gemm_dual(uint32_t ab_u32, uint32_t aoff,
                                          const char* wf1, const char* gwh,
                                          uint32_t boff,
                                          float* zout, float* swout) {
    float z0[8], z1a[8], s0[8], s1[8];
#pragma unroll
    for (int i = 0; i < 8; i++) { z0[i] = 0.f; z1a[i] = 0.f; s0[i] = 0.f; s1[i] = 0.f; }
#pragma unroll
    for (int s = 0; s < 8; s++) {
        uint32_t ah0, ah1, ah2, ah3;
        ldsm4(ah0, ah1, ah2, ah3, ab_u32 + aoff + s*32);
#pragma unroll
        for (int ntl = 0; ntl < 2; ntl++) {
            const uint4 b = *(const uint4*)(wf1 + boff + ntl*4096 + s*512);
            const uint4 w = __ldg((const uint4*)(gwh + boff + ntl*4096 + s*512));
            mma_f16(z0 + ntl*4, ah0, ah1, ah2, ah3, b.x, b.y);
            mma_f16(z1a + ntl*4, ah0, ah1, ah2, ah3, b.z, b.w);
            mma_f16(s0 + ntl*4, ah0, ah1, ah2, ah3, w.x, w.y);
            mma_f16(s1 + ntl*4, ah0, ah1, ah2, ah3, w.z, w.w);
        }
    }
#pragma unroll
    for (int i = 0; i < 8; i++) {
        zout[i]  = z0[i] + z1a[i];
        swout[i] = s0[i] + s1[i];
    }
}

// ---- prep kernels ----
__global__ void prep_mm(const float* __restrict__ A, const float* __restrict__ B,
                        int sel) {
    __shared__ float arow[H];
    const int j = blockIdx.x, k = threadIdx.x;
    arow[k] = A[j * H + k];
    __syncthreads();
    float s = 0.0f;
#pragma unroll 8
    for (int m = 0; m < H; m++) s = fmaf(arow[m], B[m * H + k], s);
    (sel ? g_Q : g_P)[j * H + k] = s;
}

__global__ void prep_frag(const float* __restrict__ W, int sel) {
    const int fi = blockIdx.x * blockDim.x + threadIdx.x;  // 0..4095
    const int ntile = fi >> 8, s = (fi >> 5) & 7, ln = fi & 31;
    const int n = ntile * 8 + (ln >> 2);
    const int k0 = s * 16 + 2 * (ln & 3);
    const float w00 = W[n*H + k0],     w01 = W[n*H + k0 + 1];
    const float w10 = W[n*H + k0 + 8], w11 = W[n*H + k0 + 9];
    uint4 v;
    pack_hl(w00, w01, v.x, v.z);
    pack_hl(w10, w11, v.y, v.w);
    char* base = (char*)(sel ? g_Whf : g_W2f) + ntile*4096 + s*512 + ln*16;
    *(uint4*)base = v;
}

__global__ void __launch_bounds__(NTH, 1)
rnnode_mma(const float* __restrict__ x, const float* __restrict__ span,
           const float* __restrict__ W_emb, const float* __restrict__ b_emb,
           const float* __restrict__ W_ih, const float* __restrict__ b_ih,
           const float* __restrict__ W_hh, const float* __restrict__ b_hh,
           const float* __restrict__ W1, const float* __restrict__ b1,
           const float* __restrict__ W2, const float* __restrict__ b2,
           const float* __restrict__ W_out, const float* __restrict__ b_out,
           float* __restrict__ out) {
    extern __shared__ char smc[];
    const uint32_t smb = smem_u32(smc);
    const int tid = threadIdx.x;
    const int lane = tid & 31, wid = tid >> 5;
    const int bb0 = blockIdx.x * NB;
    float* xs = (float*)(smc + SM_XS);

    // ---- fill SMEM weight fragment buffers (W1, P, Q), uint4 fp16 layout ----
#pragma unroll 1
    for (int m = 0; m < 3; m++) {
        const float* W = (m == 0) ? W1 : (m == 1) ? g_P : g_Q;
        char* wf = smc + (m == 0 ? SM_WF1 : m == 1 ? SM_WFP : SM_WFQ);
        for (int fi = tid; fi < 4096; fi += NTH) {
            const int ntile = fi >> 8, s = (fi >> 5) & 7, ln = fi & 31;
            const int n = ntile * 8 + (ln >> 2);
            const int k0 = s * 16 + 2 * (ln & 3);
            const float w00 = W[n*H + k0],     w01 = W[n*H + k0 + 1];
            const float w10 = W[n*H + k0 + 8], w11 = W[n*H + k0 + 9];
            uint4 v;
            pack_hl(w00, w01, v.x, v.z);
            pack_hl(w10, w11, v.y, v.w);
            *(uint4*)(wf + ntile*4096 + s*512 + ln*16) = v;
        }
    }

    // ---- per-thread fragment geometry ----
    const int g0 = lane >> 2, tq = lane & 3;
    const int r0 = g0, r1 = g0 + 8;
    const int cb0 = wid * 16 + 2 * tq;
    const uint32_t o00 = (uint32_t)(r0 * ROWB + cb0 * 2);
    const uint32_t o10 = (uint32_t)(r1 * ROWB + cb0 * 2);
    const uint32_t arow = (uint32_t)((((lane >> 3) & 1) * 8) + (lane & 7));
    const uint32_t aoff = arow * ROWB + (((lane >> 4) & 1) * 16);
    const uint32_t boff = (uint32_t)((wid * 2) * 4096 + lane * 16);

    // ---- per-col constants for cols {cb0, cb0+1, cb0+8, cb0+9} ----
    float cv[4], ccst[4], b1c[4], b2c[4], c1c[4], cwc[4];
#pragma unroll
    for (int q = 0; q < 4; q++) {
        const int col = cb0 + (q >> 1) * 8 + (q & 1);
        float vv = 0.0f, cc = 0.0f;
        for (int d = 0; d < D_IN; d++) {
            const float w = W_ih[col * D_IN + d];
            vv = fmaf(w, W_emb[d], vv);
            cc = fmaf(w, b_emb[d], cc);
        }
        cv[q] = vv;
        ccst[q] = cc + b_ih[col] + b_hh[col];
        b1c[q] = b1[col];
        b2c[q] = b2[col];
        float c1v = 0.0f, cwv = 0.0f;
        for (int k = 0; k < H; k++) {
            c1v = fmaf(b2[k], W1[col * H + k], c1v);
            cwv = fmaf(b2[k], W_hh[col * H + k], cwv);
        }
        c1c[q] = c1v;   // b2 @ W1^T
        cwc[q] = cwv;   // b2 @ Whh^T
    }
    if (tid < NB) xs[tid] = x[(size_t)(bb0 + tid) * T_SZ];
    __syncthreads();

    const uint32_t abu[2] = {smb + SM_AB0, smb + SM_AB1};
    char* abp[2] = {smc + SM_AB0, smc + SM_AB1};
    const char* wf1 = smc + SM_WF1;
    const char* wfq = smc + SM_WFQ;
    const char* gw2 = (const char*)g_W2f;
    const char* gwh = (const char*)g_Whf;

    // ---- persistent P fragments (16 uint4 = 64 regs) ----
    uint4 PB[16];
    {
        const char* wfp = smc + SM_WFP;
#pragma unroll
        for (int idx = 0; idx < 16; idx++) {
            const int s = idx >> 1, ntl = idx & 1;
            PB[idx] = *(const uint4*)(wfp + boff + ntl*4096 + s*512);
        }
    }

#define QSEL(i) (((i) >> 2) * 2 + ((i) & 1))
#define RSEL(i) ((((i) >> 1) & 1))

    // htan_0 = tanh(x_0*v + c)   (s_0 = 0 since h_0 = 0)
    float htan[8], sW[8], z1[8], u1[8], u2[8], u3[8], g[8];
    {
        const float xr[2] = {xs[r0], xs[r1]};
#pragma unroll
        for (int i = 0; i < 8; i++) {
            const int q = QSEL(i);
            htan[i] = tanh_hw(fmaf(xr[RSEL(i)], cv[q], ccst[q]));
        }
    }
    int p = 0;
    float dtL = 1.0f;

#pragma unroll 1
    for (int t = 0; t < NSTEPS; t++) {
        const float dt   = __ldg(span + t + 1) - __ldg(span + t);
        const float dt3  = dt * (1.0f / 3.0f);
        const float dt23 = 2.0f * dt3;
        const float dt8  = dt * 0.125f;
        dtL = dt;

        // L1: stage htan; dual GEMM: W1 (SMEM) -> z1, Whh (L2) -> sW
        stage8(abp[p], htan, o00, o10);
        if (tid < NB) xs[tid] = x[(size_t)(bb0 + tid) * T_SZ + (t + 1)];
        __syncthreads();
        gemm_dual(abu[p], aoff, wf1, gwh, boff, g, sW);
        p ^= 1;
#pragma unroll
        for (int i = 0; i < 8; i++) {
            z1[i] = g[i] + b1c[QSEL(i)];
            u1[i] = silu_f(z1[i]);
        }
        // L2: u2 = silu(z1 + dt/3*(u1@P^T + c1))
        stage8(abp[p], u1, o00, o10);
        __syncthreads();
        gemm32r(abu[p], aoff, PB, g);
        p ^= 1;
#pragma unroll
        for (int i = 0; i < 8; i++) {
            u2[i] = silu_f(fmaf(dt3, g[i] + c1c[QSEL(i)], z1[i]));
            g[i] = fmaf(-(1.0f / 3.0f), u1[i], u2[i]);
        }
        // L3: u3 = silu(z1 + dt*((u2-u1/3)@P^T) + 2dt/3*c1)
        stage8(abp[p], g, o00, o10);
        __syncthreads();
        gemm32r(abu[p], aoff, PB, g);
        p ^= 1;
#pragma unroll
        for (int i = 0; i < 8; i++) {
            u3[i] = silu_f(fmaf(dt, g[i], fmaf(dt23, c1c[QSEL(i)], z1[i])));
            g[i] = u1[i] - u2[i] + u3[i];
        }
        // L4: u4 = silu(z1 + dt*((u1-u2+u3)@P^T + c1)); g4 = u1+3(u2+u3)+u4
        stage8(abp[p], g, o00, o10);
        __syncthreads();
        gemm32r(abu[p], aoff, PB, g);
        p ^= 1;
#pragma unroll
        for (int i = 0; i < 8; i++) {
            const float u4 = silu_f(fmaf(dt, g[i] + c1c[QSEL(i)], z1[i]));
            g[i] = fmaf(3.0f, u2[i] + u3[i], u1[i] + u4);
        }
        // L5 (skip on last step): s+ = sW + dt/8*(g4@Q^T) + dt*cw ;
        //                         htan+ = tanh(x+*v + c + s+)
        stage8(abp[p], g, o00, o10);
        __syncthreads();
        if (t + 1 < NSTEPS) {
            gemm32s(abu[p], aoff, wfq, boff, g);
            p ^= 1;
            const float xr[2] = {xs[r0], xs[r1]};
#pragma unroll
            for (int i = 0; i < 8; i++) {
                const int q = QSEL(i);
                const float s = fmaf(dt8, g[i], fmaf(dt, cwc[q], sW[i]));
                htan[i] = tanh_hw(fmaf(xr[RSEL(i)], cv[q], ccst[q]) + s);
            }
        }
    }

    // ---- final h = htan + dt/8*(g4@W2^T) + dt*b2 (g4 staged in buf p) ----
    {
        gemm32g(abu[p], aoff, gw2, boff, g);
        const float dt8L = dtL * 0.125f;
#pragma unroll
        for (int i = 0; i < 8; i++)
            htan[i] = fmaf(dt8L, g[i], fmaf(dtL, b2c[QSEL(i)], htan[i]));
    }

    // ---- epilogue: out = h @ W_out^T + b_out ----
    __syncthreads();
    float* hb = (float*)smc;  // reuse WF1 region: [16][128] fp32
#pragma unroll
    for (int ntl = 0; ntl < 2; ntl++) {
        const int c = cb0 + ntl * 8;
        hb[r0 * H + c]     = htan[ntl*4+0];
        hb[r0 * H + c + 1] = htan[ntl*4+1];
        hb[r1 * H + c]     = htan[ntl*4+2];
        hb[r1 * H + c + 1] = htan[ntl*4+3];
    }
    __syncthreads();
    {
        const int j = tid & 63, q = tid >> 6;
        float o[4];
        const float bo = __ldg(b_out + j);
#pragma unroll
        for (int n = 0; n < 4; n++) o[n] = bo;
        const float* Wo = W_out + j * H;
#pragma unroll 4
        for (int k = 0; k < H; k++) {
            const float wv = __ldg(Wo + k);
            const float* ar = hb + (q * 4) * H + k;
#pragma unroll
            for (int n = 0; n < 4; n++) o[n] = fmaf(ar[n * H], wv, o[n]);
        }
#pragma unroll
        for (int n = 0; n < 4; n++)
            out[(size_t)(bb0 + q * 4 + n) * D_OUT + j] = o[n];
    }
}

extern "C" void kernel_launch(void* const* d_in, const int* in_sizes, int n_in,
                              void* d_out, int out_size) {
    const float* x     = (const float*)d_in[0];
    const float* span  = (const float*)d_in[1];
    const float* W_emb = (const float*)d_in[2];
    const float* b_emb = (const float*)d_in[3];
    const float* W_ih  = (const float*)d_in[4];
    const float* b_ih  = (const float*)d_in[5];
    const float* W_hh  = (const float*)d_in[6];
    const float* b_hh  = (const float*)d_in[7];
    const float* W1    = (const float*)d_in[8];
    const float* b1    = (const float*)d_in[9];
    const float* W2    = (const float*)d_in[10];
    const float* b2    = (const float*)d_in[11];
    const float* W_out = (const float*)d_in[12];
    const float* b_out = (const float*)d_in[13];
    float* out = (float*)d_out;

    prep_mm<<<H, H>>>(W1, W2, 0);     // P = W1 @ W2
    prep_mm<<<H, H>>>(W_hh, W2, 1);   // Q = Whh @ W2
    prep_frag<<<16, 256>>>(W2, 0);
    prep_frag<<<16, 256>>>(W_hh, 1);
    cudaFuncSetAttribute(rnnode_mma, cudaFuncAttributeMaxDynamicSharedMemorySize,
                         SMEM_BYTES);
    rnnode_mma<<<B_SZ / NB, NTH, SMEM_BYTES>>>(
        x, span, W_emb, b_emb, W_ih, b_ih, W_hh, b_hh,
        W1, b1, W2, b2, W_out, b_out, out);
}

// round 16
// speedup vs baseline: 9.7461x; 1.6758x over previous
#include <cuda_runtime.h>
#include <cuda_fp16.h>
#include <stdint.h>
#include <math.h>

#define B_SZ 2048
#define T_SZ 512
#define D_IN 64
#define H    128
#define D_OUT 64
#define NB   16
#define NTH  256
#define NSTEPS (T_SZ-1)
#define ROWB 272   // activation buffer row stride in bytes (128 fp16 + 16B pad)

// SMEM byte offsets (single-fp16 weight frags: 32KB each)
#define SM_WF1 0        // W1 fragments (32KB, uint2 {b0,b1} fp16)
#define SM_WFP 32768    // P fragments
#define SM_WFQ 65536    // Q fragments
#define SM_AB0 98304    // activation ping  [16][ROWB] fp16 (4352B)
#define SM_AB1 102656   // activation pong
#define SM_XS  107008   // 16 floats
#define SMEM_BYTES 107072

__device__ float g_P[H * H];               // P = W1 @ W2   (row-major [j][k])
__device__ float g_Q[H * H];               // Q = Whh @ W2  (row-major [j][k])
__device__ unsigned long long g_W2f[4096]; // W2 fragments (32KB, uint2 layout)
__device__ unsigned long long g_Whf[4096]; // Whh fragments (32KB, uint2 layout)

__device__ __forceinline__ uint32_t smem_u32(const void* p) {
    uint32_t a;
    asm("{ .reg .u64 t; cvta.to.shared.u64 t, %1; cvt.u32.u64 %0, t; }" : "=r"(a) : "l"(p));
    return a;
}
__device__ __forceinline__ uint32_t pk2h(float a, float b) {
    __half2 h = __floats2half2_rn(a, b);
    return *(uint32_t*)&h;
}
__device__ __forceinline__ void ldsm4(uint32_t& r0, uint32_t& r1, uint32_t& r2,
                                      uint32_t& r3, uint32_t addr) {
    asm volatile("ldmatrix.sync.aligned.m8n8.x4.shared.b16 {%0,%1,%2,%3}, [%4];"
                 : "=r"(r0), "=r"(r1), "=r"(r2), "=r"(r3) : "r"(addr));
}
__device__ __forceinline__ void mma_f16(float* d, uint32_t a0, uint32_t a1,
                                        uint32_t a2, uint32_t a3,
                                        uint32_t b0, uint32_t b1) {
    asm volatile("mma.sync.aligned.m16n8k16.row.col.f32.f16.f16.f32 "
                 "{%0,%1,%2,%3}, {%4,%5,%6,%7}, {%8,%9}, {%0,%1,%2,%3};"
                 : "+f"(d[0]), "+f"(d[1]), "+f"(d[2]), "+f"(d[3])
                 : "r"(a0), "r"(a1), "r"(a2), "r"(a3), "r"(b0), "r"(b1));
}
__device__ __forceinline__ float tanh_hw(float v) {
    float t;
    asm("tanh.approx.f32 %0, %1;" : "=f"(t) : "f"(v));
    return t;
}
__device__ __forceinline__ float silu_f(float v) {
    const float hv = 0.5f * v;
    return fmaf(hv, tanh_hw(hv), hv);
}

// Stage 8 fragment values as single fp16 (4 STS.32 per thread).
__device__ __forceinline__ void stage8(char* ab, const float* v,
                                       uint32_t o00, uint32_t o10) {
#pragma unroll
    for (int ntl = 0; ntl < 2; ntl++) {
        *(uint32_t*)(ab + o00 + ntl*16) = pk2h(v[ntl*4+0], v[ntl*4+1]);
        *(uint32_t*)(ab + o10 + ntl*16) = pk2h(v[ntl*4+2], v[ntl*4+3]);
    }
}

// Weight fragment uint2 layout: addr = ntile*2048 + s*256 + lane*8 ; v = {b0, b1}

// GEMM, weights from SMEM: single term, 2 chains of 8.
__device__ __forceinline__ void gemm16s(uint32_t ab_u32, uint32_t aoff,
                                        const char* wf, uint32_t boff,
                                        float* dout) {
#pragma unroll
    for (int i = 0; i < 8; i++) dout[i] = 0.f;
#pragma unroll
    for (int s = 0; s < 8; s++) {
        uint32_t ah0, ah1, ah2, ah3;
        ldsm4(ah0, ah1, ah2, ah3, ab_u32 + aoff + s*32);
#pragma unroll
        for (int ntl = 0; ntl < 2; ntl++) {
            const uint2 b = *(const uint2*)(wf + boff + ntl*2048 + s*256);
            mma_f16(dout + ntl*4, ah0, ah1, ah2, ah3, b.x, b.y);
        }
    }
}

// GEMM, weights from persistent registers (P matrix).
__device__ __forceinline__ void gemm16r(uint32_t ab_u32, uint32_t aoff,
                                        const uint2* PB, float* dout) {
#pragma unroll
    for (int i = 0; i < 8; i++) dout[i] = 0.f;
#pragma unroll
    for (int s = 0; s < 8; s++) {
        uint32_t ah0, ah1, ah2, ah3;
        ldsm4(ah0, ah1, ah2, ah3, ab_u32 + aoff + s*32);
#pragma unroll
        for (int ntl = 0; ntl < 2; ntl++) {
            const uint2 b = PB[s*2 + ntl];
            mma_f16(dout + ntl*4, ah0, ah1, ah2, ah3, b.x, b.y);
        }
    }
}

// GEMM, weights streamed from global (L2), prefetched.
__device__ __forceinline__ void gemm16g(uint32_t ab_u32, uint32_t aoff,
                                        const char* gw, uint32_t boff,
                                        float* dout) {
    uint2 B[16];
#pragma unroll
    for (int s = 0; s < 8; s++)
#pragma unroll
        for (int ntl = 0; ntl < 2; ntl++)
            B[s*2+ntl] = __ldg((const uint2*)(gw + boff + ntl*2048 + s*256));
#pragma unroll
    for (int i = 0; i < 8; i++) dout[i] = 0.f;
#pragma unroll
    for (int s = 0; s < 8; s++) {
        uint32_t ah0, ah1, ah2, ah3;
        ldsm4(ah0, ah1, ah2, ah3, ab_u32 + aoff + s*32);
#pragma unroll
        for (int ntl = 0; ntl < 2; ntl++) {
            const uint2 b = B[s*2+ntl];
            mma_f16(dout + ntl*4, ah0, ah1, ah2, ah3, b.x, b.y);
        }
    }
}

// L1 dual GEMM: W1 (SMEM) -> zout and Whh (pre-fetched regs WH) -> swout.
__device__ __forceinline__ void gemm_dual(uint32_t ab_u32, uint32_t aoff,
                                          const char* wf1, const uint2* WH,
                                          uint32_t boff,
                                          float* zout, float* swout) {
#pragma unroll
    for (int i = 0; i < 8; i++) { zout[i] = 0.f; swout[i] = 0.f; }
#pragma unroll
    for (int s = 0; s < 8; s++) {
        uint32_t ah0, ah1, ah2, ah3;
        ldsm4(ah0, ah1, ah2, ah3, ab_u32 + aoff + s*32);
#pragma unroll
        for (int ntl = 0; ntl < 2; ntl++) {
            const uint2 b = *(const uint2*)(wf1 + boff + ntl*2048 + s*256);
            const uint2 w = WH[s*2 + ntl];
            mma_f16(zout + ntl*4, ah0, ah1, ah2, ah3, b.x, b.y);
            mma_f16(swout + ntl*4, ah0, ah1, ah2, ah3, w.x, w.y);
        }
    }
}

// ---- prep kernels ----
__global__ void prep_mm(const float* __restrict__ A, const float* __restrict__ B,
                        int sel) {
    __shared__ float arow[H];
    const int j = blockIdx.x, k = threadIdx.x;
    arow[k] = A[j * H + k];
    __syncthreads();
    float s = 0.0f;
#pragma unroll 8
    for (int m = 0; m < H; m++) s = fmaf(arow[m], B[m * H + k], s);
    (sel ? g_Q : g_P)[j * H + k] = s;
}

__global__ void prep_frag(const float* __restrict__ W, int sel) {
    const int fi = blockIdx.x * blockDim.x + threadIdx.x;  // 0..4095
    const int ntile = fi >> 8, s = (fi >> 5) & 7, ln = fi & 31;
    const int n = ntile * 8 + (ln >> 2);
    const int k0 = s * 16 + 2 * (ln & 3);
    uint2 v;
    v.x = pk2h(W[n*H + k0],     W[n*H + k0 + 1]);
    v.y = pk2h(W[n*H + k0 + 8], W[n*H + k0 + 9]);
    char* base = (char*)(sel ? g_Whf : g_W2f) + ntile*2048 + s*256 + ln*8;
    *(uint2*)base = v;
}

__global__ void __launch_bounds__(NTH, 1)
rnnode_mma(const float* __restrict__ x, const float* __restrict__ span,
           const float* __restrict__ W_emb, const float* __restrict__ b_emb,
           const float* __restrict__ W_ih, const float* __restrict__ b_ih,
           const float* __restrict__ W_hh, const float* __restrict__ b_hh,
           const float* __restrict__ W1, const float* __restrict__ b1,
           const float* __restrict__ W2, const float* __restrict__ b2,
           const float* __restrict__ W_out, const float* __restrict__ b_out,
           float* __restrict__ out) {
    extern __shared__ char smc[];
    const uint32_t smb = smem_u32(smc);
    const int tid = threadIdx.x;
    const int lane = tid & 31, wid = tid >> 5;
    const int bb0 = blockIdx.x * NB;
    float* xs = (float*)(smc + SM_XS);

    // ---- fill SMEM weight fragment buffers (W1, P, Q), uint2 fp16 layout ----
#pragma unroll 1
    for (int m = 0; m < 3; m++) {
        const float* W = (m == 0) ? W1 : (m == 1) ? g_P : g_Q;
        char* wf = smc + (m == 0 ? SM_WF1 : m == 1 ? SM_WFP : SM_WFQ);
        for (int fi = tid; fi < 4096; fi += NTH) {
            const int ntile = fi >> 8, s = (fi >> 5) & 7, ln = fi & 31;
            const int n = ntile * 8 + (ln >> 2);
            const int k0 = s * 16 + 2 * (ln & 3);
            uint2 v;
            v.x = pk2h(W[n*H + k0],     W[n*H + k0 + 1]);
            v.y = pk2h(W[n*H + k0 + 8], W[n*H + k0 + 9]);
            *(uint2*)(wf + ntile*2048 + s*256 + ln*8) = v;
        }
    }

    // ---- per-thread fragment geometry ----
    const int g0 = lane >> 2, tq = lane & 3;
    const int r0 = g0, r1 = g0 + 8;
    const int cb0 = wid * 16 + 2 * tq;
    const uint32_t o00 = (uint32_t)(r0 * ROWB + cb0 * 2);
    const uint32_t o10 = (uint32_t)(r1 * ROWB + cb0 * 2);
    const uint32_t arow = (uint32_t)((((lane >> 3) & 1) * 8) + (lane & 7));
    const uint32_t aoff = arow * ROWB + (((lane >> 4) & 1) * 16);
    const uint32_t boff = (uint32_t)((wid * 2) * 2048 + lane * 8);

    // ---- per-col constants for cols {cb0, cb0+1, cb0+8, cb0+9} ----
    float cv[4], ccst[4], b1c[4], b2c[4], c1c[4], cwc[4];
#pragma unroll
    for (int q = 0; q < 4; q++) {
        const int col = cb0 + (q >> 1) * 8 + (q & 1);
        float vv = 0.0f, cc = 0.0f;
        for (int d = 0; d < D_IN; d++) {
            const float w = W_ih[col * D_IN + d];
            vv = fmaf(w, W_emb[d], vv);
            cc = fmaf(w, b_emb[d], cc);
        }
        cv[q] = vv;
        ccst[q] = cc + b_ih[col] + b_hh[col];
        b1c[q] = b1[col];
        b2c[q] = b2[col];
        float c1v = 0.0f, cwv = 0.0f;
        for (int k = 0; k < H; k++) {
            c1v = fmaf(b2[k], W1[col * H + k], c1v);
            cwv = fmaf(b2[k], W_hh[col * H + k], cwv);
        }
        c1c[q] = c1v;   // b2 @ W1^T
        cwc[q] = cwv;   // b2 @ Whh^T
    }
    if (tid < NB) xs[tid] = x[(size_t)(bb0 + tid) * T_SZ];
    __syncthreads();

    const uint32_t abu[2] = {smb + SM_AB0, smb + SM_AB1};
    char* abp[2] = {smc + SM_AB0, smc + SM_AB1};
    const char* wf1 = smc + SM_WF1;
    const char* wfq = smc + SM_WFQ;
    const char* gw2 = (const char*)g_W2f;
    const char* gwh = (const char*)g_Whf;

    // ---- persistent P fragments (16 uint2 = 32 regs) ----
    uint2 PB[16];
    {
        const char* wfp = smc + SM_WFP;
#pragma unroll
        for (int idx = 0; idx < 16; idx++) {
            const int s = idx >> 1, ntl = idx & 1;
            PB[idx] = *(const uint2*)(wfp + boff + ntl*2048 + s*256);
        }
    }

#define QSEL(i) (((i) >> 2) * 2 + ((i) & 1))
#define RSEL(i) ((((i) >> 1) & 1))

    // htan_0 = tanh(x_0*v + c)   (s_0 = 0 since h_0 = 0)
    float htan[8], sW[8], z1[8], u1[8], u2[8], u3[8], g[8];
    {
        const float xr[2] = {xs[r0], xs[r1]};
#pragma unroll
        for (int i = 0; i < 8; i++) {
            const int q = QSEL(i);
            htan[i] = tanh_hw(fmaf(xr[RSEL(i)], cv[q], ccst[q]));
        }
    }
    int p = 0;
    float dtL = 1.0f;

#pragma unroll 1
    for (int t = 0; t < NSTEPS; t++) {
        const float dt   = __ldg(span + t + 1) - __ldg(span + t);
        const float dt3  = dt * (1.0f / 3.0f);
        const float dt23 = 2.0f * dt3;
        const float dt8  = dt * 0.125f;
        dtL = dt;

        // Prefetch Whh frags (independent of staging -> L2 latency hides
        // under stage + barrier).
        uint2 WH[16];
#pragma unroll
        for (int idx = 0; idx < 16; idx++) {
            const int s = idx >> 1, ntl = idx & 1;
            WH[idx] = __ldg((const uint2*)(gwh + boff + ntl*2048 + s*256));
        }

        // L1: stage htan; dual GEMM: W1 (SMEM) -> z1, Whh (regs) -> sW
        stage8(abp[p], htan, o00, o10);
        if (tid < NB) xs[tid] = x[(size_t)(bb0 + tid) * T_SZ + (t + 1)];
        __syncthreads();
        gemm_dual(abu[p], aoff, wf1, WH, boff, g, sW);
        p ^= 1;
#pragma unroll
        for (int i = 0; i < 8; i++) {
            z1[i] = g[i] + b1c[QSEL(i)];
            u1[i] = silu_f(z1[i]);
        }
        // L2: u2 = silu(z1 + dt/3*(u1@P^T + c1))
        stage8(abp[p], u1, o00, o10);
        __syncthreads();
        gemm16r(abu[p], aoff, PB, g);
        p ^= 1;
#pragma unroll
        for (int i = 0; i < 8; i++) {
            u2[i] = silu_f(fmaf(dt3, g[i] + c1c[QSEL(i)], z1[i]));
            g[i] = fmaf(-(1.0f / 3.0f), u1[i], u2[i]);
        }
        // L3: u3 = silu(z1 + dt*((u2-u1/3)@P^T) + 2dt/3*c1)
        stage8(abp[p], g, o00, o10);
        __syncthreads();
        gemm16r(abu[p], aoff, PB, g);
        p ^= 1;
#pragma unroll
        for (int i = 0; i < 8; i++) {
            u3[i] = silu_f(fmaf(dt, g[i], fmaf(dt23, c1c[QSEL(i)], z1[i])));
            g[i] = u1[i] - u2[i] + u3[i];
        }
        // L4: u4 = silu(z1 + dt*((u1-u2+u3)@P^T + c1)); g4 = u1+3(u2+u3)+u4
        stage8(abp[p], g, o00, o10);
        __syncthreads();
        gemm16r(abu[p], aoff, PB, g);
        p ^= 1;
#pragma unroll
        for (int i = 0; i < 8; i++) {
            const float u4 = silu_f(fmaf(dt, g[i] + c1c[QSEL(i)], z1[i]));
            g[i] = fmaf(3.0f, u2[i] + u3[i], u1[i] + u4);
        }
        // L5 (skip on last step): s+ = sW + dt/8*(g4@Q^T) + dt*cw ;
        //                         htan+ = tanh(x+*v + c + s+)
        stage8(abp[p], g, o00, o10);
        __syncthreads();
        if (t + 1 < NSTEPS) {
            gemm16s(abu[p], aoff, wfq, boff, g);
            p ^= 1;
            const float xr[2] = {xs[r0], xs[r1]};
#pragma unroll
            for (int i = 0; i < 8; i++) {
                const int q = QSEL(i);
                const float s = fmaf(dt8, g[i], fmaf(dt, cwc[q], sW[i]));
                htan[i] = tanh_hw(fmaf(xr[RSEL(i)], cv[q], ccst[q]) + s);
            }
        }
    }

    // ---- final h = htan + dt/8*(g4@W2^T) + dt*b2 (g4 staged in buf p) ----
    {
        gemm16g(abu[p], aoff, gw2, boff, g);
        const float dt8L = dtL * 0.125f;
#pragma unroll
        for (int i = 0; i < 8; i++)
            htan[i] = fmaf(dt8L, g[i], fmaf(dtL, b2c[QSEL(i)], htan[i]));
    }

    // ---- epilogue: out = h @ W_out^T + b_out ----
    __syncthreads();
    float* hb = (float*)smc;  // reuse WF1 region: [16][128] fp32
#pragma unroll
    for (int ntl = 0; ntl < 2; ntl++) {
        const int c = cb0 + ntl * 8;
        hb[r0 * H + c]     = htan[ntl*4+0];
        hb[r0 * H + c + 1] = htan[ntl*4+1];
        hb[r1 * H + c]     = htan[ntl*4+2];
        hb[r1 * H + c + 1] = htan[ntl*4+3];
    }
    __syncthreads();
    {
        const int j = tid & 63, q = tid >> 6;
        float o[4];
        const float bo = __ldg(b_out + j);
#pragma unroll
        for (int n = 0; n < 4; n++) o[n] = bo;
        const float* Wo = W_out + j * H;
#pragma unroll 4
        for (int k = 0; k < H; k++) {
            const float wv = __ldg(Wo + k);
            const float* ar = hb + (q * 4) * H + k;
#pragma unroll
            for (int n = 0; n < 4; n++) o[n] = fmaf(ar[n * H], wv, o[n]);
        }
#pragma unroll
        for (int n = 0; n < 4; n++)
            out[(size_t)(bb0 + q * 4 + n) * D_OUT + j] = o[n];
    }
}

extern "C" void kernel_launch(void* const* d_in, const int* in_sizes, int n_in,
                              void* d_out, int out_size) {
    const float* x     = (const float*)d_in[0];
    const float* span  = (const float*)d_in[1];
    const float* W_emb = (const float*)d_in[2];
    const float* b_emb = (const float*)d_in[3];
    const float* W_ih  = (const float*)d_in[4];
    const float* b_ih  = (const float*)d_in[5];
    const float* W_hh  = (const float*)d_in[6];
    const float* b_hh  = (const float*)d_in[7];
    const float* W1    = (const float*)d_in[8];
    const float* b1    = (const float*)d_in[9];
    const float* W2    = (const float*)d_in[10];
    const float* b2    = (const float*)d_in[11];
    const float* W_out = (const float*)d_in[12];
    const float* b_out = (const float*)d_in[13];
    float* out = (float*)d_out;

    prep_mm<<<H, H>>>(W1, W2, 0);     // P = W1 @ W2
    prep_mm<<<H, H>>>(W_hh, W2, 1);   // Q = Whh @ W2
    prep_frag<<<16, 256>>>(W2, 0);
    prep_frag<<<16, 256>>>(W_hh, 1);
    cudaFuncSetAttribute(rnnode_mma, cudaFuncAttributeMaxDynamicSharedMemorySize,
                         SMEM_BYTES);
    rnnode_mma<<<B_SZ / NB, NTH, SMEM_BYTES>>>(
        x, span, W_emb, b_emb, W_ih, b_ih, W_hh, b_hh,
        W1, b1, W2, b2, W_out, b_out, out);
}